// round 4
// baseline (speedup 1.0000x reference)
#include <cuda_runtime.h>
#include <cstdint>
#include <cmath>

#define BATCH 8192

// ---------------- persistent device scratch (no allocations allowed) --------
__device__ uint32_t g_xbits[BATCH * 28];          // [n][p] bits over q (28)
__device__ int      g_T0[28 * 28];                // [q][p] column sums of +-1
__device__ unsigned long long g_w1lo[32];         // rows 0..6 of 9x9 window (63 bits)
__device__ uint32_t g_w1hi[32];                   // rows 7..8 (18 bits)
__device__ int      g_pthr1[32];                  // integer popcount thresholds
__device__ uint32_t g_A1[BATCH * 400];            // [n][h][w] bits over c (32)
__device__ int      g_T1[32 * 400];               // [c][p*20+q]
__device__ uint32_t g_w2b[81 * 16];               // [(i*9+j)*16 + c] bits over k (32)
__device__ int      g_pthr2[16];
__device__ uint32_t g_A2[BATCH * 144];            // [n][h][w] bits over c (16, low half)
__device__ int      g_T2[16 * 144];               // [c][p*12+q]
__device__ uint32_t g_w3b[81 * 8];                // [(i*9+j)*8 + c] bits over k (16)
__device__ int      g_pthr3[8];
__device__ uint32_t g_wlb[40];                    // [cl][4] 128-bit masks
__device__ float    g_bls[10];                    // sign(bl)

// ---------------- weight preparation ----------------------------------------
__global__ void k_prep(const float* __restrict__ w1, const float* __restrict__ w2,
                       const float* __restrict__ w3, const float* __restrict__ wl,
                       const float* __restrict__ bl) {
    int t = threadIdx.x;
    // w1: pack 9x9 window into (lo64, hi32) per output channel
    for (int c = t; c < 32; c += blockDim.x) {
        unsigned long long lo = 0ull; uint32_t hi = 0u;
        for (int i = 0; i < 9; i++)
            for (int j = 0; j < 9; j++) {
                int bit = (w1[c * 81 + i * 9 + j] >= 0.f);
                if (i < 7) lo |= (unsigned long long)bit << (i * 9 + j);
                else       hi |= (uint32_t)bit << ((i - 7) * 9 + j);
            }
        g_w1lo[c] = lo; g_w1hi[c] = hi;
    }
    // w2: per (i,j) per out-channel, 32 input-channel bits
    for (int idx = t; idx < 81 * 16; idx += blockDim.x) {
        int ij = idx >> 4, c = idx & 15;
        uint32_t w = 0u;
        for (int k = 0; k < 32; k++)
            w |= (uint32_t)(w2[(c * 32 + k) * 81 + ij] >= 0.f) << k;
        g_w2b[ij * 16 + c] = w;
    }
    // w3: per (i,j) per out-channel, 16 input-channel bits
    for (int idx = t; idx < 81 * 8; idx += blockDim.x) {
        int ij = idx >> 3, c = idx & 7;
        uint32_t w = 0u;
        for (int k = 0; k < 16; k++)
            w |= (uint32_t)(w3[(c * 16 + k) * 81 + ij] >= 0.f) << k;
        g_w3b[ij * 8 + c] = w;
    }
    // wl: 10 classes x 128 bits. bit layout: word tt -> channels 2tt (low16), 2tt+1 (high16); pos = h*4+w
    for (int cl = t; cl < 10; cl += blockDim.x) {
        for (int tt = 0; tt < 4; tt++) {
            uint32_t w = 0u;
            for (int pos = 0; pos < 16; pos++) {
                w |= (uint32_t)(wl[(cl * 8 + 2 * tt)     * 16 + pos] >= 0.f) << pos;
                w |= (uint32_t)(wl[(cl * 8 + 2 * tt + 1) * 16 + pos] >= 0.f) << (pos + 16);
            }
            g_wlb[cl * 4 + tt] = w;
        }
        g_bls[cl] = (bl[cl] >= 0.f) ? 1.f : -1.f;
    }
}

// ---------------- input binarize + pack --------------------------------------
__global__ void k_pack(const float* __restrict__ x) {
    int t = blockIdx.x * blockDim.x + threadIdx.x;   // (n,p) row index
    if (t >= BATCH * 28) return;
    const float4* r = (const float4*)(x + (size_t)t * 28);
    uint32_t w = 0u;
#pragma unroll
    for (int v = 0; v < 7; v++) {
        float4 f = r[v];
        w |= (uint32_t)(f.x >= 0.f) << (v * 4 + 0);
        w |= (uint32_t)(f.y >= 0.f) << (v * 4 + 1);
        w |= (uint32_t)(f.z >= 0.f) << (v * 4 + 2);
        w |= (uint32_t)(f.w >= 0.f) << (v * 4 + 3);
    }
    g_xbits[t] = w;
}

// ---------------- generic bit-column counter (warp ballot) -------------------
// src: [n][NPOS] words; dst[c*NPOS + pos] = sum_n (2*bit-1)
template <int NBITS, int NPOS>
__device__ __forceinline__ void count_impl(const uint32_t* __restrict__ src,
                                           int* __restrict__ dst) {
    int pos  = blockIdx.x;
    int lane = threadIdx.x & 31, warp = threadIdx.x >> 5;
    const int nwarp = 8;                // blockDim = 256
    const int per   = BATCH / (32 * nwarp);
    int cnt = 0;
    for (int it = 0; it < per; it++) {
        int n = (warp * per + it) * 32 + lane;
        uint32_t v = src[(size_t)n * NPOS + pos];
#pragma unroll
        for (int c = 0; c < NBITS; c++) {
            uint32_t m = __ballot_sync(0xFFFFFFFFu, (v >> c) & 1u);
            if (lane == c) cnt += __popc(m);
        }
    }
    __shared__ int s[32];
    if (threadIdx.x < 32) s[threadIdx.x] = 0;
    __syncthreads();
    if (lane < NBITS) atomicAdd(&s[lane], cnt);
    __syncthreads();
    if (threadIdx.x < NBITS)
        dst[threadIdx.x * NPOS + pos] = 2 * s[threadIdx.x] - BATCH;
}

__global__ void k_count_T0() { count_impl<28, 28>(g_xbits, g_T0); }
__global__ void k_count_T1() { count_impl<32, 400>(g_A1, g_T1); }
__global__ void k_count_T2() { count_impl<16, 144>(g_A2, g_T2); }

// ---------------- threshold kernels ------------------------------------------
__global__ void k_thresh1(const float* __restrict__ w1) {
    __shared__ long long U[81];
    int t = threadIdx.x;
    if (t < 81) {
        int i = t / 9, j = t % 9;
        long long s = 0;
        for (int h = 0; h < 20; h++)
            for (int w = 0; w < 20; w++)
                s += g_T0[(w + j) * 28 + (h + i)];
        U[t] = s;
    }
    __syncthreads();
    if (t < 32) {
        long long acc = 0;
        for (int ij = 0; ij < 81; ij++)
            acc += (w1[t * 81 + ij] >= 0.f) ? U[ij] : -U[ij];
        double m = (double)acc / (8192.0 * 400.0);
        g_pthr1[t] = (int)floor((81.0 - m) * 0.5);
    }
}

__global__ void k_thresh2(const float* __restrict__ w2) {
    __shared__ long long U[32 * 81];
    int t = threadIdx.x;
    for (int idx = t; idx < 32 * 81; idx += blockDim.x) {
        int k = idx / 81, ij = idx % 81, i = ij / 9, j = ij % 9;
        long long s = 0;
        for (int h = 0; h < 12; h++)
            for (int w = 0; w < 12; w++)
                s += g_T1[k * 400 + (h + i) * 20 + (w + j)];
        U[idx] = s;
    }
    __syncthreads();
    if (t < 16) {
        long long acc = 0;
        for (int k = 0; k < 32; k++)
            for (int ij = 0; ij < 81; ij++)
                acc += (w2[(t * 32 + k) * 81 + ij] >= 0.f) ? U[k * 81 + ij] : -U[k * 81 + ij];
        double m = (double)acc / (8192.0 * 144.0);
        g_pthr2[t] = (int)floor((2592.0 - m) * 0.5);
    }
}

__global__ void k_thresh3(const float* __restrict__ w3) {
    __shared__ long long U[16 * 81];
    int t = threadIdx.x;
    for (int idx = t; idx < 16 * 81; idx += blockDim.x) {
        int k = idx / 81, ij = idx % 81, i = ij / 9, j = ij % 9;
        long long s = 0;
        for (int h = 0; h < 4; h++)
            for (int w = 0; w < 4; w++)
                s += g_T2[k * 144 + (h + i) * 12 + (w + j)];
        U[idx] = s;
    }
    __syncthreads();
    if (t < 8) {
        long long acc = 0;
        for (int k = 0; k < 16; k++)
            for (int ij = 0; ij < 81; ij++)
                acc += (w3[(t * 16 + k) * 81 + ij] >= 0.f) ? U[k * 81 + ij] : -U[k * 81 + ij];
        double m = (double)acc / (8192.0 * 16.0);
        g_pthr3[t] = (int)floor((1296.0 - m) * 0.5);
    }
}

// ---------------- layer 1: 1->32, 28x28 -> 20x20 -----------------------------
__global__ void __launch_bounds__(256) k_layer1() {
    __shared__ unsigned long long swlo[32];
    __shared__ uint32_t swhi[32];
    __shared__ int spt[32];
    int t = threadIdx.x;
    if (t < 32) { swlo[t] = g_w1lo[t]; swhi[t] = g_w1hi[t]; spt[t] = g_pthr1[t]; }
    __syncthreads();
    int gid = blockIdx.x * 256 + t;       // (n,h,w), grid exact
    int n = gid / 400, r = gid % 400, h = r / 20, w = r % 20;
    const uint32_t* rows = &g_xbits[n * 28 + h];
    uint32_t e[9];
#pragma unroll
    for (int i = 0; i < 9; i++) e[i] = (rows[i] >> w) & 0x1FFu;
    unsigned long long lo = (unsigned long long)e[0]
        | ((unsigned long long)e[1] << 9)  | ((unsigned long long)e[2] << 18)
        | ((unsigned long long)e[3] << 27) | ((unsigned long long)e[4] << 36)
        | ((unsigned long long)e[5] << 45) | ((unsigned long long)e[6] << 54);
    uint32_t hi = e[7] | (e[8] << 9);
    uint32_t word = 0u;
#pragma unroll
    for (int c = 0; c < 32; c++) {
        int p = __popcll(lo ^ swlo[c]) + __popc(hi ^ swhi[c]);
        word |= (uint32_t)(p <= spt[c]) << c;
    }
    g_A1[gid] = word;
}

// ---------------- layer 2: 32->16, 20x20 -> 12x12 (hot) ----------------------
// block = 288 threads = 4 samples x 72 workers; worker = (h, 4-wide w tile, 8-chan group)
__global__ void __launch_bounds__(288) k_layer2() {
    __shared__ __align__(16) uint32_t img[4 * 400];
    __shared__ __align__(16) uint32_t wsh[81 * 16];
    __shared__ int spt[16];
    __shared__ uint32_t outw[4 * 144];
    int t = threadIdx.x;
    int n0 = blockIdx.x * 4;
    for (int idx = t; idx < 1600; idx += 288) img[idx] = g_A1[(size_t)n0 * 400 + idx];
    for (int idx = t; idx < 1296; idx += 288) wsh[idx] = g_w2b[idx];
    if (t < 16) spt[t] = g_pthr2[t];
    for (int idx = t; idx < 576; idx += 288) outw[idx] = 0u;
    __syncthreads();

    int s  = t / 72,  r  = t - s * 72;
    int cg = r / 36,  rr = r - cg * 36;
    int h  = rr / 3,  wt = rr - h * 3;
    int w0 = wt * 4;
    const uint32_t* im = img + s * 400;

    uint32_t acc[8][4];
#pragma unroll
    for (int cc = 0; cc < 8; cc++)
#pragma unroll
        for (int ww = 0; ww < 4; ww++) acc[cc][ww] = 0u;

    for (int i = 0; i < 9; i++) {
        const uint4* ap = (const uint4*)(im + (h + i) * 20 + w0);
        uint4 a0 = ap[0], a1 = ap[1], a2 = ap[2];
        uint32_t a[12] = {a0.x, a0.y, a0.z, a0.w, a1.x, a1.y, a1.z, a1.w,
                          a2.x, a2.y, a2.z, a2.w};
#pragma unroll
        for (int j = 0; j < 9; j++) {
            const uint4* wp = (const uint4*)(wsh + (i * 9 + j) * 16 + cg * 8);
            uint4 wv0 = wp[0], wv1 = wp[1];
            uint32_t wr[8] = {wv0.x, wv0.y, wv0.z, wv0.w, wv1.x, wv1.y, wv1.z, wv1.w};
#pragma unroll
            for (int cc = 0; cc < 8; cc++)
#pragma unroll
                for (int ww = 0; ww < 4; ww++)
                    acc[cc][ww] += __popc(a[j + ww] ^ wr[cc]);
        }
    }
#pragma unroll
    for (int ww = 0; ww < 4; ww++) {
        uint32_t byte = 0u;
#pragma unroll
        for (int cc = 0; cc < 8; cc++)
            byte |= (uint32_t)((int)acc[cc][ww] <= spt[cg * 8 + cc]) << cc;
        atomicOr(&outw[s * 144 + h * 12 + w0 + ww], byte << (cg * 8));
    }
    __syncthreads();
    for (int idx = t; idx < 576; idx += 288) g_A2[(size_t)n0 * 144 + idx] = outw[idx];
}

// ---------------- layers 3+4 fused: 16->8 conv, 12x12->4x4, then 10-class ----
// block = 128 threads = 4 warps = 8 samples (16 lanes/sample, one per 4x4 pos)
__global__ void __launch_bounds__(128) k_layer34(float* __restrict__ out) {
    __shared__ uint32_t img[8 * 144];
    __shared__ __align__(16) uint32_t w3s[81 * 8];
    __shared__ int spt[8];
    __shared__ uint32_t wls[40];
    __shared__ float bls[10];
    int t = threadIdx.x;
    int n0 = blockIdx.x * 8;
    for (int idx = t; idx < 1152; idx += 128) img[idx] = g_A2[(size_t)n0 * 144 + idx];
    for (int idx = t; idx < 648; idx += 128) w3s[idx] = g_w3b[idx];
    if (t < 8)  spt[t] = g_pthr3[t];
    if (t < 40) wls[t] = g_wlb[t];
    if (t < 10) bls[t] = g_bls[t];
    __syncthreads();

    int warp = t >> 5, lane = t & 31;
    int sb  = warp * 2 + (lane >> 4);       // sample in block
    int pos = lane & 15, h = pos >> 2, w = pos & 3;
    const uint32_t* im = img + sb * 144;

    int acc[8] = {0, 0, 0, 0, 0, 0, 0, 0};
    for (int i = 0; i < 9; i++) {
#pragma unroll
        for (int j = 0; j < 9; j++) {
            uint32_t a = im[(h + i) * 12 + (w + j)];
            const uint4* wp = (const uint4*)(w3s + (i * 9 + j) * 8);
            uint4 w0v = wp[0], w1v = wp[1];
            acc[0] += __popc(a ^ w0v.x); acc[1] += __popc(a ^ w0v.y);
            acc[2] += __popc(a ^ w0v.z); acc[3] += __popc(a ^ w0v.w);
            acc[4] += __popc(a ^ w1v.x); acc[5] += __popc(a ^ w1v.y);
            acc[6] += __popc(a ^ w1v.z); acc[7] += __popc(a ^ w1v.w);
        }
    }
    uint32_t bb[8];
#pragma unroll
    for (int c = 0; c < 8; c++)
        bb[c] = __ballot_sync(0xFFFFFFFFu, acc[c] <= spt[c]);
    int sh = (lane >> 4) * 16;
    uint32_t W[4];
#pragma unroll
    for (int tt = 0; tt < 4; tt++)
        W[tt] = ((bb[2 * tt] >> sh) & 0xFFFFu) | (((bb[2 * tt + 1] >> sh) & 0xFFFFu) << 16);
    if (pos < 10) {
        int cl = pos;
        int sm = __popc(W[0] ^ wls[cl * 4 + 0]) + __popc(W[1] ^ wls[cl * 4 + 1])
               + __popc(W[2] ^ wls[cl * 4 + 2]) + __popc(W[3] ^ wls[cl * 4 + 3]);
        out[(size_t)(n0 + sb) * 10 + cl] = (float)(128 - 2 * sm) + bls[cl];
    }
}

// ---------------- launch ------------------------------------------------------
extern "C" void kernel_launch(void* const* d_in, const int* in_sizes, int n_in,
                              void* d_out, int out_size) {
    const float* x  = (const float*)d_in[0];
    const float* w1 = (const float*)d_in[1];
    const float* w2 = (const float*)d_in[3];
    const float* w3 = (const float*)d_in[5];
    const float* wl = (const float*)d_in[7];
    const float* bl = (const float*)d_in[8];
    float* out = (float*)d_out;

    k_prep<<<1, 256>>>(w1, w2, w3, wl, bl);
    k_pack<<<(BATCH * 28) / 256, 256>>>(x);
    k_count_T0<<<28, 256>>>();
    k_thresh1<<<1, 128>>>(w1);
    k_layer1<<<(BATCH * 400) / 256, 256>>>();
    k_count_T1<<<400, 256>>>();
    k_thresh2<<<1, 1024>>>(w2);
    k_layer2<<<BATCH / 4, 288>>>();
    k_count_T2<<<144, 256>>>();
    k_thresh3<<<1, 256>>>(w3);
    k_layer34<<<BATCH / 8, 128>>>(out);
}

// round 5
// speedup vs baseline: 1.3493x; 1.3493x over previous
#include <cuda_runtime.h>
#include <cstdint>
#include <cmath>

#define BATCH 8192

// ---------------- persistent device scratch (no allocations allowed) --------
__device__ uint32_t g_xbits[BATCH * 28];          // [n][p] bits over q (28)
__device__ int      g_T0[28 * 28];                // [q][p]
__device__ unsigned long long g_w1lo[32];
__device__ uint32_t g_w1hi[32];
__device__ int      g_pthr1[32];
__device__ uint32_t g_A1t[400 * BATCH];           // [pos][n]  (transposed)
__device__ int      g_P1[256 * 12800];            // T1 partials [blk][pos*32+c]
__device__ int      g_T1[32 * 400];               // [c][pos]
__device__ uint32_t g_w2b[81 * 16];
__device__ int      g_pthr2[16];
__device__ uint32_t g_A2t[144 * BATCH];           // [pos][n]  (transposed)
__device__ int      g_T2[16 * 144];               // [c][pos]
__device__ uint32_t g_w3b[81 * 8];
__device__ int      g_pthr3[8];
__device__ uint32_t g_wlb[40];
__device__ float    g_bls[10];

// ---------------- input binarize + pack (coalesced float4 reads) -------------
__global__ void k_pack(const float* __restrict__ x) {
    int t = blockIdx.x * blockDim.x + threadIdx.x;   // (n,p) row index
    if (t >= BATCH * 28) return;
    const float4* r = (const float4*)(x + (size_t)t * 28);
    uint32_t w = 0u;
#pragma unroll
    for (int v = 0; v < 7; v++) {
        float4 f = r[v];
        w |= (uint32_t)(f.x >= 0.f) << (v * 4 + 0);
        w |= (uint32_t)(f.y >= 0.f) << (v * 4 + 1);
        w |= (uint32_t)(f.z >= 0.f) << (v * 4 + 2);
        w |= (uint32_t)(f.w >= 0.f) << (v * 4 + 3);
    }
    g_xbits[t] = w;
}

// ---------------- T0 count: block per row p, ballot over samples -------------
__global__ void __launch_bounds__(256) k_count_T0() {
    __shared__ int scnt[28];
    int p = blockIdx.x;
    int t = threadIdx.x, lane = t & 31, warp = t >> 5;
    if (t < 28) scnt[t] = 0;
    __syncthreads();
    int cnt = 0;
    const int per = BATCH / (32 * 8);
    for (int it = 0; it < per; it++) {
        int n = (warp * per + it) * 32 + lane;
        uint32_t v = g_xbits[n * 28 + p];
#pragma unroll
        for (int q = 0; q < 28; q++) {
            uint32_t m = __ballot_sync(0xFFFFFFFFu, (v >> q) & 1u);
            if (lane == q) cnt += __popc(m);
        }
    }
    if (lane < 28) atomicAdd(&scnt[lane], cnt);
    __syncthreads();
    if (t < 28) g_T0[t * 28 + p] = 2 * scnt[t] - BATCH;
}

// ---------------- thresh1: pack w1 + threshold (parallel, smem) --------------
__global__ void __launch_bounds__(256) k_thresh1(const float* __restrict__ w1) {
    __shared__ int sT0[784];
    __shared__ long long U[81];
    int t = threadIdx.x;
    for (int i = t; i < 784; i += 256) sT0[i] = g_T0[i];
    unsigned long long lo = 0ull; uint32_t hi = 0u;
    if (t < 32) {
        for (int i = 0; i < 9; i++)
            for (int j = 0; j < 9; j++) {
                int bit = (w1[t * 81 + i * 9 + j] >= 0.f);
                if (i < 7) lo |= (unsigned long long)bit << (i * 9 + j);
                else       hi |= (uint32_t)bit << ((i - 7) * 9 + j);
            }
        g_w1lo[t] = lo; g_w1hi[t] = hi;
    }
    __syncthreads();
    if (t < 81) {
        int i = t / 9, j = t % 9;
        long long s = 0;
        for (int h = 0; h < 20; h++)
#pragma unroll
            for (int w = 0; w < 20; w++)
                s += sT0[(w + j) * 28 + (h + i)];
        U[t] = s;
    }
    __syncthreads();
    if (t < 32) {
        long long acc = 0;
        for (int ij = 0; ij < 81; ij++) {
            int i = ij / 9, j = ij % 9;
            int bit = (i < 7) ? (int)((lo >> ij) & 1ull)
                              : (int)((hi >> ((i - 7) * 9 + j)) & 1u);
            acc += bit ? U[ij] : -U[ij];
        }
        double m = (double)acc / (8192.0 * 400.0);
        g_pthr1[t] = (int)floor((81.0 - m) * 0.5);
    }
}

// ---------------- layer1 fused with T1 counting ------------------------------
// block = 32 samples x 8 warps; warp handles 50 positions, lanes = samples.
__global__ void __launch_bounds__(256) k_layer1ct() {
    __shared__ uint32_t rows[32 * 28];
    __shared__ unsigned long long swlo[32];
    __shared__ uint32_t swhi[32];
    __shared__ int spt[32];
    int t = threadIdx.x, lane = t & 31, warp = t >> 5;
    int n0 = blockIdx.x * 32;
    for (int i = t; i < 896; i += 256) rows[i] = g_xbits[n0 * 28 + i];
    if (t < 32) { swlo[t] = g_w1lo[t]; swhi[t] = g_w1hi[t]; spt[t] = g_pthr1[t]; }
    __syncthreads();
    const uint32_t* r = rows + lane * 28;
    for (int pp = 0; pp < 50; pp++) {
        int pos = warp * 50 + pp;
        int h = pos / 20, w = pos % 20;
        uint32_t e[9];
#pragma unroll
        for (int i = 0; i < 9; i++) e[i] = (r[h + i] >> w) & 0x1FFu;
        unsigned long long lo = (unsigned long long)e[0]
            | ((unsigned long long)e[1] << 9)  | ((unsigned long long)e[2] << 18)
            | ((unsigned long long)e[3] << 27) | ((unsigned long long)e[4] << 36)
            | ((unsigned long long)e[5] << 45) | ((unsigned long long)e[6] << 54);
        uint32_t hi = e[7] | (e[8] << 9);
        uint32_t word = 0u;
        int myCnt = 0;
#pragma unroll
        for (int c = 0; c < 32; c++) {
            int p = __popcll(lo ^ swlo[c]) + __popc(hi ^ swhi[c]);
            unsigned bit = (p <= spt[c]);
            word |= bit << c;
            uint32_t m = __ballot_sync(0xFFFFFFFFu, bit);
            if (lane == c) myCnt = __popc(m);
        }
        g_A1t[(size_t)pos * BATCH + n0 + lane] = word;     // coalesced
        g_P1[blockIdx.x * 12800 + pos * 32 + lane] = myCnt; // coalesced
    }
}

// ---------------- reduce T1 partials ----------------------------------------
__global__ void __launch_bounds__(256) k_redT1() {
    int idx = blockIdx.x * 256 + threadIdx.x;     // 12800
    if (idx >= 12800) return;
    int s = 0;
    for (int b = 0; b < 256; b++) s += g_P1[b * 12800 + idx];
    int pos = idx >> 5, c = idx & 31;
    g_T1[c * 400 + pos] = 2 * s - BATCH;
}

// ---------------- thresh2: pack w2b + threshold (parallel, smem) -------------
__global__ void __launch_bounds__(1024) k_thresh2(const float* __restrict__ w2) {
    __shared__ short sT1[12800];
    __shared__ int sU[2592];
    __shared__ uint32_t sw2b[1296];
    int t = threadIdx.x;
    for (int idx = t; idx < 1296; idx += 1024) {
        int ij = idx >> 4, c = idx & 15;
        uint32_t w = 0u;
        for (int k = 0; k < 32; k++)
            w |= (uint32_t)(w2[(c * 32 + k) * 81 + ij] >= 0.f) << k;
        sw2b[idx] = w; g_w2b[idx] = w;
    }
    for (int idx = t; idx < 12800; idx += 1024) sT1[idx] = (short)g_T1[idx];
    __syncthreads();
    for (int idx = t; idx < 2592; idx += 1024) {
        int k = idx / 81, ij = idx % 81, i = ij / 9, j = ij % 9;
        int s = 0;
        const short* base = sT1 + k * 400 + i * 20 + j;
        for (int h = 0; h < 12; h++)
#pragma unroll
            for (int w = 0; w < 12; w++)
                s += base[h * 20 + w];
        sU[idx] = s;
    }
    __syncthreads();
    int warp = t >> 5, lane = t & 31;
    if (warp < 16) {
        int k = lane;
        int a32 = 0;
        for (int ij = 0; ij < 81; ij++) {
            int u = sU[k * 81 + ij];
            a32 += ((sw2b[ij * 16 + warp] >> k) & 1u) ? u : -u;
        }
        long long a = a32;
#pragma unroll
        for (int off = 16; off; off >>= 1)
            a += __shfl_down_sync(0xFFFFFFFFu, a, off);
        if (lane == 0) {
            double m = (double)a / (8192.0 * 144.0);
            g_pthr2[warp] = (int)floor((2592.0 - m) * 0.5);
        }
    }
}

// ---------------- layer 2: 32->16, 20x20 -> 12x12 (hot) ----------------------
__global__ void __launch_bounds__(288) k_layer2() {
    __shared__ __align__(16) uint32_t img[4 * 400];
    __shared__ __align__(16) uint32_t wsh[81 * 16];
    __shared__ int spt[16];
    __shared__ uint32_t outw[4 * 144];
    int t = threadIdx.x;
    int n0 = blockIdx.x * 4;
    for (int idx = t; idx < 1600; idx += 288) {
        int pos = idx >> 2, s = idx & 3;
        img[s * 400 + pos] = g_A1t[(size_t)pos * BATCH + n0 + s];
    }
    for (int idx = t; idx < 1296; idx += 288) wsh[idx] = g_w2b[idx];
    if (t < 16) spt[t] = g_pthr2[t];
    for (int idx = t; idx < 576; idx += 288) outw[idx] = 0u;
    __syncthreads();

    int s  = t / 72,  r  = t - s * 72;
    int cg = r / 36,  rr = r - cg * 36;
    int h  = rr / 3,  wt = rr - h * 3;
    int w0 = wt * 4;
    const uint32_t* im = img + s * 400;

    uint32_t acc[8][4];
#pragma unroll
    for (int cc = 0; cc < 8; cc++)
#pragma unroll
        for (int ww = 0; ww < 4; ww++) acc[cc][ww] = 0u;

    for (int i = 0; i < 9; i++) {
        const uint4* ap = (const uint4*)(im + (h + i) * 20 + w0);
        uint4 a0 = ap[0], a1 = ap[1], a2 = ap[2];
        uint32_t a[12] = {a0.x, a0.y, a0.z, a0.w, a1.x, a1.y, a1.z, a1.w,
                          a2.x, a2.y, a2.z, a2.w};
#pragma unroll
        for (int j = 0; j < 9; j++) {
            const uint4* wp = (const uint4*)(wsh + (i * 9 + j) * 16 + cg * 8);
            uint4 wv0 = wp[0], wv1 = wp[1];
            uint32_t wr[8] = {wv0.x, wv0.y, wv0.z, wv0.w, wv1.x, wv1.y, wv1.z, wv1.w};
#pragma unroll
            for (int cc = 0; cc < 8; cc++)
#pragma unroll
                for (int ww = 0; ww < 4; ww++)
                    acc[cc][ww] += __popc(a[j + ww] ^ wr[cc]);
        }
    }
#pragma unroll
    for (int ww = 0; ww < 4; ww++) {
        uint32_t byte = 0u;
#pragma unroll
        for (int cc = 0; cc < 8; cc++)
            byte |= (uint32_t)((int)acc[cc][ww] <= spt[cg * 8 + cc]) << cc;
        atomicOr(&outw[s * 144 + h * 12 + w0 + ww], byte << (cg * 8));
    }
    __syncthreads();
    for (int idx = t; idx < 576; idx += 288) {
        int pos = idx >> 2, ss = idx & 3;
        g_A2t[(size_t)pos * BATCH + n0 + ss] = outw[ss * 144 + pos];
    }
}

// ---------------- T2 count: block per pos, ballot over samples (coalesced) ---
__global__ void __launch_bounds__(256) k_count_T2() {
    __shared__ int scnt[16];
    int pos = blockIdx.x;
    int t = threadIdx.x, lane = t & 31, warp = t >> 5;
    if (t < 16) scnt[t] = 0;
    __syncthreads();
    int cnt = 0;
    const int per = BATCH / (32 * 8);
    for (int it = 0; it < per; it++) {
        int n = (warp * per + it) * 32 + lane;
        uint32_t v = g_A2t[(size_t)pos * BATCH + n];
#pragma unroll
        for (int c = 0; c < 16; c++) {
            uint32_t m = __ballot_sync(0xFFFFFFFFu, (v >> c) & 1u);
            if (lane == c) cnt += __popc(m);
        }
    }
    if (lane < 16) atomicAdd(&scnt[lane], cnt);
    __syncthreads();
    if (t < 16) g_T2[t * 144 + pos] = 2 * scnt[t] - BATCH;
}

// ---------------- thresh3: pack w3b/wl/bl + threshold ------------------------
__global__ void __launch_bounds__(1024) k_thresh3(const float* __restrict__ w3,
                                                  const float* __restrict__ wl,
                                                  const float* __restrict__ bl) {
    __shared__ short sT2[2304];
    __shared__ int sU[16 * 81];
    __shared__ uint32_t sw3b[648];
    int t = threadIdx.x;
    for (int idx = t; idx < 648; idx += 1024) {
        int ij = idx >> 3, c = idx & 7;
        uint32_t w = 0u;
        for (int k = 0; k < 16; k++)
            w |= (uint32_t)(w3[(c * 16 + k) * 81 + ij] >= 0.f) << k;
        sw3b[idx] = w; g_w3b[idx] = w;
    }
    for (int idx = t; idx < 2304; idx += 1024) sT2[idx] = (short)g_T2[idx];
    if (t < 10) {
        for (int tt = 0; tt < 4; tt++) {
            uint32_t w = 0u;
            for (int pos = 0; pos < 16; pos++) {
                w |= (uint32_t)(wl[(t * 8 + 2 * tt)     * 16 + pos] >= 0.f) << pos;
                w |= (uint32_t)(wl[(t * 8 + 2 * tt + 1) * 16 + pos] >= 0.f) << (pos + 16);
            }
            g_wlb[t * 4 + tt] = w;
        }
        g_bls[t] = (bl[t] >= 0.f) ? 1.f : -1.f;
    }
    __syncthreads();
    for (int idx = t; idx < 1296; idx += 1024) {
        int k = idx / 81, ij = idx % 81, i = ij / 9, j = ij % 9;
        int s = 0;
        const short* base = sT2 + k * 144 + i * 12 + j;
#pragma unroll
        for (int h = 0; h < 4; h++)
#pragma unroll
            for (int w = 0; w < 4; w++) s += base[h * 12 + w];
        sU[idx] = s;
    }
    __syncthreads();
    int warp = t >> 5, lane = t & 31;
    if (warp < 8) {
        long long acc = 0;
        if (lane < 16) {
            int k = lane, a = 0;
            for (int ij = 0; ij < 81; ij++) {
                int u = sU[k * 81 + ij];
                a += ((sw3b[ij * 8 + warp] >> k) & 1u) ? u : -u;
            }
            acc = a;
        }
#pragma unroll
        for (int off = 16; off; off >>= 1)
            acc += __shfl_down_sync(0xFFFFFFFFu, acc, off);
        if (lane == 0) {
            double m = (double)acc / (8192.0 * 16.0);
            g_pthr3[warp] = (int)floor((1296.0 - m) * 0.5);
        }
    }
}

// ---------------- layers 3+4 fused -------------------------------------------
__global__ void __launch_bounds__(128) k_layer34(float* __restrict__ out) {
    __shared__ uint32_t img[8 * 144];
    __shared__ __align__(16) uint32_t w3s[81 * 8];
    __shared__ int spt[8];
    __shared__ uint32_t wls[40];
    __shared__ float bls[10];
    int t = threadIdx.x;
    int n0 = blockIdx.x * 8;
    for (int idx = t; idx < 1152; idx += 128) {
        int pos = idx >> 3, s = idx & 7;
        img[s * 144 + pos] = g_A2t[(size_t)pos * BATCH + n0 + s];
    }
    for (int idx = t; idx < 648; idx += 128) w3s[idx] = g_w3b[idx];
    if (t < 8)  spt[t] = g_pthr3[t];
    if (t < 40) wls[t] = g_wlb[t];
    if (t < 10) bls[t] = g_bls[t];
    __syncthreads();

    int warp = t >> 5, lane = t & 31;
    int sb  = warp * 2 + (lane >> 4);
    int pos = lane & 15, h = pos >> 2, w = pos & 3;
    const uint32_t* im = img + sb * 144;

    int acc[8] = {0, 0, 0, 0, 0, 0, 0, 0};
    for (int i = 0; i < 9; i++) {
#pragma unroll
        for (int j = 0; j < 9; j++) {
            uint32_t a = im[(h + i) * 12 + (w + j)];
            const uint4* wp = (const uint4*)(w3s + (i * 9 + j) * 8);
            uint4 w0v = wp[0], w1v = wp[1];
            acc[0] += __popc(a ^ w0v.x); acc[1] += __popc(a ^ w0v.y);
            acc[2] += __popc(a ^ w0v.z); acc[3] += __popc(a ^ w0v.w);
            acc[4] += __popc(a ^ w1v.x); acc[5] += __popc(a ^ w1v.y);
            acc[6] += __popc(a ^ w1v.z); acc[7] += __popc(a ^ w1v.w);
        }
    }
    uint32_t bb[8];
#pragma unroll
    for (int c = 0; c < 8; c++)
        bb[c] = __ballot_sync(0xFFFFFFFFu, acc[c] <= spt[c]);
    int sh = (lane >> 4) * 16;
    uint32_t W[4];
#pragma unroll
    for (int tt = 0; tt < 4; tt++)
        W[tt] = ((bb[2 * tt] >> sh) & 0xFFFFu) | (((bb[2 * tt + 1] >> sh) & 0xFFFFu) << 16);
    if (pos < 10) {
        int cl = pos;
        int sm = __popc(W[0] ^ wls[cl * 4 + 0]) + __popc(W[1] ^ wls[cl * 4 + 1])
               + __popc(W[2] ^ wls[cl * 4 + 2]) + __popc(W[3] ^ wls[cl * 4 + 3]);
        out[(size_t)(n0 + sb) * 10 + cl] = (float)(128 - 2 * sm) + bls[cl];
    }
}

// ---------------- launch ------------------------------------------------------
extern "C" void kernel_launch(void* const* d_in, const int* in_sizes, int n_in,
                              void* d_out, int out_size) {
    const float* x  = (const float*)d_in[0];
    const float* w1 = (const float*)d_in[1];
    const float* w2 = (const float*)d_in[3];
    const float* w3 = (const float*)d_in[5];
    const float* wl = (const float*)d_in[7];
    const float* bl = (const float*)d_in[8];
    float* out = (float*)d_out;

    k_pack<<<(BATCH * 28) / 256, 256>>>(x);
    k_count_T0<<<28, 256>>>();
    k_thresh1<<<1, 256>>>(w1);
    k_layer1ct<<<256, 256>>>();
    k_redT1<<<50, 256>>>();
    k_thresh2<<<1, 1024>>>(w2);
    k_layer2<<<BATCH / 4, 288>>>();
    k_count_T2<<<144, 256>>>();
    k_thresh3<<<1, 1024>>>(w3, wl, bl);
    k_layer34<<<BATCH / 8, 128>>>(out);
}

// round 6
// speedup vs baseline: 1.3534x; 1.0030x over previous
#include <cuda_runtime.h>
#include <cstdint>
#include <cmath>

#define BATCH 8192

// ---------------- persistent device scratch (no allocations allowed) --------
__device__ uint32_t g_xbits[BATCH * 28];          // [n][p] bits over q (28)
__device__ int      g_T0[28 * 28];                // [q][p]
__device__ unsigned long long g_w1lo[32];
__device__ uint32_t g_w1hi[32];
__device__ int      g_pthr1[32];
__device__ unsigned short g_A1lo[400 * BATCH];    // [pos][n] channels 0..15
__device__ unsigned short g_A1hi[400 * BATCH];    // [pos][n] channels 16..31
__device__ int      g_T1[32 * 400];               // [c][pos]
__device__ uint32_t g_w2b[81 * 16];
__device__ int      g_pthr2[16];
__device__ uint32_t g_A2t[144 * BATCH];           // [pos][n]
__device__ int      g_T2[16 * 144];               // [c][pos]
__device__ uint32_t g_w3b[81 * 8];
__device__ int      g_pthr3[8];
__device__ uint32_t g_wlb[40];
__device__ float    g_bls[10];

// ---------------- input binarize + pack (coalesced float4 reads) -------------
__global__ void k_pack(const float* __restrict__ x) {
    int t = blockIdx.x * blockDim.x + threadIdx.x;   // (n,p) row index
    if (t >= BATCH * 28) return;
    const float4* r = (const float4*)(x + (size_t)t * 28);
    uint32_t w = 0u;
#pragma unroll
    for (int v = 0; v < 7; v++) {
        float4 f = r[v];
        w |= (uint32_t)(f.x >= 0.f) << (v * 4 + 0);
        w |= (uint32_t)(f.y >= 0.f) << (v * 4 + 1);
        w |= (uint32_t)(f.z >= 0.f) << (v * 4 + 2);
        w |= (uint32_t)(f.w >= 0.f) << (v * 4 + 3);
    }
    g_xbits[t] = w;
}

// ---------------- T0 count: block per row p, ballot over samples -------------
__global__ void __launch_bounds__(256) k_count_T0() {
    __shared__ int scnt[28];
    int p = blockIdx.x;
    int t = threadIdx.x, lane = t & 31, warp = t >> 5;
    if (t < 28) scnt[t] = 0;
    __syncthreads();
    int cnt = 0;
    const int per = BATCH / (32 * 8);
    for (int it = 0; it < per; it++) {
        int n = (warp * per + it) * 32 + lane;
        uint32_t v = g_xbits[n * 28 + p];
#pragma unroll
        for (int q = 0; q < 28; q++) {
            uint32_t m = __ballot_sync(0xFFFFFFFFu, (v >> q) & 1u);
            if (lane == q) cnt += __popc(m);
        }
    }
    if (lane < 28) atomicAdd(&scnt[lane], cnt);
    __syncthreads();
    if (t < 28) g_T0[t * 28 + p] = 2 * scnt[t] - BATCH;
}

// ---------------- thresh1: pack w1 + threshold (parallel, smem) --------------
__global__ void __launch_bounds__(256) k_thresh1(const float* __restrict__ w1) {
    __shared__ int sT0[784];
    __shared__ long long U[81];
    int t = threadIdx.x;
    for (int i = t; i < 784; i += 256) sT0[i] = g_T0[i];
    unsigned long long lo = 0ull; uint32_t hi = 0u;
    if (t < 32) {
        for (int i = 0; i < 9; i++)
            for (int j = 0; j < 9; j++) {
                int bit = (w1[t * 81 + i * 9 + j] >= 0.f);
                if (i < 7) lo |= (unsigned long long)bit << (i * 9 + j);
                else       hi |= (uint32_t)bit << ((i - 7) * 9 + j);
            }
        g_w1lo[t] = lo; g_w1hi[t] = hi;
    }
    __syncthreads();
    if (t < 81) {
        int i = t / 9, j = t % 9;
        long long s = 0;
        for (int h = 0; h < 20; h++)
#pragma unroll
            for (int w = 0; w < 20; w++)
                s += sT0[(w + j) * 28 + (h + i)];
        U[t] = s;
    }
    __syncthreads();
    if (t < 32) {
        long long acc = 0;
        for (int ij = 0; ij < 81; ij++) {
            int i = ij / 9, j = ij % 9;
            int bit = (i < 7) ? (int)((lo >> ij) & 1ull)
                              : (int)((hi >> ((i - 7) * 9 + j)) & 1u);
            acc += bit ? U[ij] : -U[ij];
        }
        double m = (double)acc / (8192.0 * 400.0);
        g_pthr1[t] = (int)floor((81.0 - m) * 0.5);
    }
}

// ---------------- layer1: 1->32, split 16-channel x 100-position blocks ------
// grid = 256 sample-groups x 8 (4 pos-groups x 2 chan-groups); block = 128 (4 warps)
// lane = sample within group of 32; warp handles 25 positions.
__global__ void __launch_bounds__(128) k_layer1() {
    __shared__ uint32_t rows[32 * 29];            // padded stride 29: conflict-free
    int t = threadIdx.x, lane = t & 31, warp = t >> 5;
    int bx = blockIdx.x;
    int sg = bx >> 3, pg = bx & 7;
    int cg = pg & 1, pq = pg >> 1;                // 16-chan group, 100-pos group
    int n0 = sg * 32;
    for (int i = t; i < 896; i += 128) {
        int n = i / 28, p = i - n * 28;
        rows[n * 29 + p] = g_xbits[(n0 + n) * 28 + p];
    }
    unsigned long long wlo[16]; uint32_t whi[16]; int thr[16];
#pragma unroll
    for (int k = 0; k < 16; k++) {
        int c = cg * 16 + k;
        wlo[k] = g_w1lo[c]; whi[k] = g_w1hi[c]; thr[k] = g_pthr1[c];
    }
    __syncthreads();
    const uint32_t* r = rows + lane * 29;
    unsigned short* dst = cg ? g_A1hi : g_A1lo;
    for (int pp = 0; pp < 25; pp++) {
        int pos = pq * 100 + warp * 25 + pp;
        int h = pos / 20, w = pos - h * 20;
        uint32_t e[9];
#pragma unroll
        for (int i = 0; i < 9; i++) e[i] = (r[h + i] >> w) & 0x1FFu;
        unsigned long long lo = (unsigned long long)e[0]
            | ((unsigned long long)e[1] << 9)  | ((unsigned long long)e[2] << 18)
            | ((unsigned long long)e[3] << 27) | ((unsigned long long)e[4] << 36)
            | ((unsigned long long)e[5] << 45) | ((unsigned long long)e[6] << 54);
        uint32_t hi = e[7] | (e[8] << 9);
        uint32_t word = 0u;
#pragma unroll
        for (int k = 0; k < 16; k++) {
            int p = __popcll(lo ^ wlo[k]) + __popc(hi ^ whi[k]);
            word |= (uint32_t)(p <= thr[k]) << k;
        }
        dst[(size_t)pos * BATCH + n0 + lane] = (unsigned short)word;
    }
}

// ---------------- T1 count: block per pos, ballot over samples (coalesced) ---
__global__ void __launch_bounds__(256) k_count_T1() {
    __shared__ int scnt[32];
    int pos = blockIdx.x;
    int t = threadIdx.x, lane = t & 31, warp = t >> 5;
    if (t < 32) scnt[t] = 0;
    __syncthreads();
    int cnt = 0;
    const int per = BATCH / 256;
    const size_t base = (size_t)pos * BATCH;
    for (int it = 0; it < per; it++) {
        int n = (warp * per + it) * 32 + lane;
        uint32_t v = (uint32_t)g_A1lo[base + n] | ((uint32_t)g_A1hi[base + n] << 16);
#pragma unroll
        for (int c = 0; c < 32; c++) {
            uint32_t m = __ballot_sync(0xFFFFFFFFu, (v >> c) & 1u);
            if (lane == c) cnt += __popc(m);
        }
    }
    atomicAdd(&scnt[lane], cnt);
    __syncthreads();
    if (t < 32) g_T1[t * 400 + pos] = 2 * scnt[t] - BATCH;
}

// ---------------- thresh2: pack w2b + threshold (parallel, smem) -------------
__global__ void __launch_bounds__(1024) k_thresh2(const float* __restrict__ w2) {
    __shared__ short sT1[12800];
    __shared__ int sU[2592];
    __shared__ uint32_t sw2b[1296];
    int t = threadIdx.x;
    for (int idx = t; idx < 1296; idx += 1024) {
        int ij = idx >> 4, c = idx & 15;
        uint32_t w = 0u;
        for (int k = 0; k < 32; k++)
            w |= (uint32_t)(w2[(c * 32 + k) * 81 + ij] >= 0.f) << k;
        sw2b[idx] = w; g_w2b[idx] = w;
    }
    for (int idx = t; idx < 12800; idx += 1024) sT1[idx] = (short)g_T1[idx];
    __syncthreads();
    for (int idx = t; idx < 2592; idx += 1024) {
        int k = idx / 81, ij = idx % 81, i = ij / 9, j = ij % 9;
        int s = 0;
        const short* base = sT1 + k * 400 + i * 20 + j;
        for (int h = 0; h < 12; h++)
#pragma unroll
            for (int w = 0; w < 12; w++)
                s += base[h * 20 + w];
        sU[idx] = s;
    }
    __syncthreads();
    int warp = t >> 5, lane = t & 31;
    if (warp < 16) {
        int k = lane;
        int a32 = 0;
        for (int ij = 0; ij < 81; ij++) {
            int u = sU[k * 81 + ij];
            a32 += ((sw2b[ij * 16 + warp] >> k) & 1u) ? u : -u;
        }
        long long a = a32;
#pragma unroll
        for (int off = 16; off; off >>= 1)
            a += __shfl_down_sync(0xFFFFFFFFu, a, off);
        if (lane == 0) {
            double m = (double)a / (8192.0 * 144.0);
            g_pthr2[warp] = (int)floor((2592.0 - m) * 0.5);
        }
    }
}

// ---------------- layer 2: 32->16, 20x20 -> 12x12 (hot) ----------------------
// block = 288 threads = 4 samples x 72 workers; worker = (h, 4-wide w tile, 8-chan group)
// accumulators packed 2-per-register (16-bit halves) to cut register pressure.
__global__ void __launch_bounds__(288) k_layer2() {
    __shared__ __align__(16) uint32_t img[4 * 400];
    __shared__ __align__(16) uint32_t wsh[81 * 16];
    __shared__ int spt[16];
    __shared__ uint32_t outw[4 * 144];
    int t = threadIdx.x;
    int n0 = blockIdx.x * 4;
    for (int idx = t; idx < 1600; idx += 288) {
        int pos = idx >> 2, s = idx & 3;
        size_t g = (size_t)pos * BATCH + n0 + s;
        img[s * 400 + pos] = (uint32_t)g_A1lo[g] | ((uint32_t)g_A1hi[g] << 16);
    }
    for (int idx = t; idx < 1296; idx += 288) wsh[idx] = g_w2b[idx];
    if (t < 16) spt[t] = g_pthr2[t];
    for (int idx = t; idx < 576; idx += 288) outw[idx] = 0u;
    __syncthreads();

    int s  = t / 72,  r  = t - s * 72;
    int cg = r / 36,  rr = r - cg * 36;
    int h  = rr / 3,  wt = rr - h * 3;
    int w0 = wt * 4;
    const uint32_t* im = img + s * 400;

    uint32_t acc[8][2];                            // [chan][wpair], 16-bit halves
#pragma unroll
    for (int cc = 0; cc < 8; cc++) { acc[cc][0] = 0u; acc[cc][1] = 0u; }

    for (int i = 0; i < 9; i++) {
        const uint4* ap = (const uint4*)(im + (h + i) * 20 + w0);
        uint4 a0 = ap[0], a1 = ap[1], a2 = ap[2];
        uint32_t a[12] = {a0.x, a0.y, a0.z, a0.w, a1.x, a1.y, a1.z, a1.w,
                          a2.x, a2.y, a2.z, a2.w};
#pragma unroll
        for (int j = 0; j < 9; j++) {
            const uint4* wp = (const uint4*)(wsh + (i * 9 + j) * 16 + cg * 8);
            uint4 wv0 = wp[0], wv1 = wp[1];
            uint32_t wr[8] = {wv0.x, wv0.y, wv0.z, wv0.w, wv1.x, wv1.y, wv1.z, wv1.w};
#pragma unroll
            for (int cc = 0; cc < 8; cc++) {
                acc[cc][0] += __popc(a[j + 0] ^ wr[cc]) + (__popc(a[j + 1] ^ wr[cc]) << 16);
                acc[cc][1] += __popc(a[j + 2] ^ wr[cc]) + (__popc(a[j + 3] ^ wr[cc]) << 16);
            }
        }
    }
#pragma unroll
    for (int ww = 0; ww < 4; ww++) {
        uint32_t byte = 0u;
#pragma unroll
        for (int cc = 0; cc < 8; cc++) {
            int v = (ww & 1) ? (int)(acc[cc][ww >> 1] >> 16)
                             : (int)(acc[cc][ww >> 1] & 0xFFFFu);
            byte |= (uint32_t)(v <= spt[cg * 8 + cc]) << cc;
        }
        atomicOr(&outw[s * 144 + h * 12 + w0 + ww], byte << (cg * 8));
    }
    __syncthreads();
    for (int idx = t; idx < 576; idx += 288) {
        int pos = idx >> 2, ss = idx & 3;
        g_A2t[(size_t)pos * BATCH + n0 + ss] = outw[ss * 144 + pos];
    }
}

// ---------------- T2 count: block per pos, ballot over samples (coalesced) ---
__global__ void __launch_bounds__(256) k_count_T2() {
    __shared__ int scnt[16];
    int pos = blockIdx.x;
    int t = threadIdx.x, lane = t & 31, warp = t >> 5;
    if (t < 16) scnt[t] = 0;
    __syncthreads();
    int cnt = 0;
    const int per = BATCH / (32 * 8);
    for (int it = 0; it < per; it++) {
        int n = (warp * per + it) * 32 + lane;
        uint32_t v = g_A2t[(size_t)pos * BATCH + n];
#pragma unroll
        for (int c = 0; c < 16; c++) {
            uint32_t m = __ballot_sync(0xFFFFFFFFu, (v >> c) & 1u);
            if (lane == c) cnt += __popc(m);
        }
    }
    if (lane < 16) atomicAdd(&scnt[lane], cnt);
    __syncthreads();
    if (t < 16) g_T2[t * 144 + pos] = 2 * scnt[t] - BATCH;
}

// ---------------- thresh3: pack w3b/wl/bl + threshold ------------------------
__global__ void __launch_bounds__(1024) k_thresh3(const float* __restrict__ w3,
                                                  const float* __restrict__ wl,
                                                  const float* __restrict__ bl) {
    __shared__ short sT2[2304];
    __shared__ int sU[16 * 81];
    __shared__ uint32_t sw3b[648];
    int t = threadIdx.x;
    for (int idx = t; idx < 648; idx += 1024) {
        int ij = idx >> 3, c = idx & 7;
        uint32_t w = 0u;
        for (int k = 0; k < 16; k++)
            w |= (uint32_t)(w3[(c * 16 + k) * 81 + ij] >= 0.f) << k;
        sw3b[idx] = w; g_w3b[idx] = w;
    }
    for (int idx = t; idx < 2304; idx += 1024) sT2[idx] = (short)g_T2[idx];
    if (t < 10) {
        for (int tt = 0; tt < 4; tt++) {
            uint32_t w = 0u;
            for (int pos = 0; pos < 16; pos++) {
                w |= (uint32_t)(wl[(t * 8 + 2 * tt)     * 16 + pos] >= 0.f) << pos;
                w |= (uint32_t)(wl[(t * 8 + 2 * tt + 1) * 16 + pos] >= 0.f) << (pos + 16);
            }
            g_wlb[t * 4 + tt] = w;
        }
        g_bls[t] = (bl[t] >= 0.f) ? 1.f : -1.f;
    }
    __syncthreads();
    for (int idx = t; idx < 1296; idx += 1024) {
        int k = idx / 81, ij = idx % 81, i = ij / 9, j = ij % 9;
        int s = 0;
        const short* base = sT2 + k * 144 + i * 12 + j;
#pragma unroll
        for (int h = 0; h < 4; h++)
#pragma unroll
            for (int w = 0; w < 4; w++) s += base[h * 12 + w];
        sU[idx] = s;
    }
    __syncthreads();
    int warp = t >> 5, lane = t & 31;
    if (warp < 8) {
        long long acc = 0;
        if (lane < 16) {
            int k = lane, a = 0;
            for (int ij = 0; ij < 81; ij++) {
                int u = sU[k * 81 + ij];
                a += ((sw3b[ij * 8 + warp] >> k) & 1u) ? u : -u;
            }
            acc = a;
        }
#pragma unroll
        for (int off = 16; off; off >>= 1)
            acc += __shfl_down_sync(0xFFFFFFFFu, acc, off);
        if (lane == 0) {
            double m = (double)acc / (8192.0 * 16.0);
            g_pthr3[warp] = (int)floor((1296.0 - m) * 0.5);
        }
    }
}

// ---------------- layers 3+4 fused -------------------------------------------
__global__ void __launch_bounds__(128) k_layer34(float* __restrict__ out) {
    __shared__ uint32_t img[8 * 144];
    __shared__ __align__(16) uint32_t w3s[81 * 8];
    __shared__ int spt[8];
    __shared__ uint32_t wls[40];
    __shared__ float bls[10];
    int t = threadIdx.x;
    int n0 = blockIdx.x * 8;
    for (int idx = t; idx < 1152; idx += 128) {
        int pos = idx >> 3, s = idx & 7;
        img[s * 144 + pos] = g_A2t[(size_t)pos * BATCH + n0 + s];
    }
    for (int idx = t; idx < 648; idx += 128) w3s[idx] = g_w3b[idx];
    if (t < 8)  spt[t] = g_pthr3[t];
    if (t < 40) wls[t] = g_wlb[t];
    if (t < 10) bls[t] = g_bls[t];
    __syncthreads();

    int warp = t >> 5, lane = t & 31;
    int sb  = warp * 2 + (lane >> 4);
    int pos = lane & 15, h = pos >> 2, w = pos & 3;
    const uint32_t* im = img + sb * 144;

    int acc[8] = {0, 0, 0, 0, 0, 0, 0, 0};
    for (int i = 0; i < 9; i++) {
#pragma unroll
        for (int j = 0; j < 9; j++) {
            uint32_t a = im[(h + i) * 12 + (w + j)];
            const uint4* wp = (const uint4*)(w3s + (i * 9 + j) * 8);
            uint4 w0v = wp[0], w1v = wp[1];
            acc[0] += __popc(a ^ w0v.x); acc[1] += __popc(a ^ w0v.y);
            acc[2] += __popc(a ^ w0v.z); acc[3] += __popc(a ^ w0v.w);
            acc[4] += __popc(a ^ w1v.x); acc[5] += __popc(a ^ w1v.y);
            acc[6] += __popc(a ^ w1v.z); acc[7] += __popc(a ^ w1v.w);
        }
    }
    uint32_t bb[8];
#pragma unroll
    for (int c = 0; c < 8; c++)
        bb[c] = __ballot_sync(0xFFFFFFFFu, acc[c] <= spt[c]);
    int sh = (lane >> 4) * 16;
    uint32_t W[4];
#pragma unroll
    for (int tt = 0; tt < 4; tt++)
        W[tt] = ((bb[2 * tt] >> sh) & 0xFFFFu) | (((bb[2 * tt + 1] >> sh) & 0xFFFFu) << 16);
    if (pos < 10) {
        int cl = pos;
        int sm = __popc(W[0] ^ wls[cl * 4 + 0]) + __popc(W[1] ^ wls[cl * 4 + 1])
               + __popc(W[2] ^ wls[cl * 4 + 2]) + __popc(W[3] ^ wls[cl * 4 + 3]);
        out[(size_t)(n0 + sb) * 10 + cl] = (float)(128 - 2 * sm) + bls[cl];
    }
}

// ---------------- launch ------------------------------------------------------
extern "C" void kernel_launch(void* const* d_in, const int* in_sizes, int n_in,
                              void* d_out, int out_size) {
    const float* x  = (const float*)d_in[0];
    const float* w1 = (const float*)d_in[1];
    const float* w2 = (const float*)d_in[3];
    const float* w3 = (const float*)d_in[5];
    const float* wl = (const float*)d_in[7];
    const float* bl = (const float*)d_in[8];
    float* out = (float*)d_out;

    k_pack<<<(BATCH * 28) / 256, 256>>>(x);
    k_count_T0<<<28, 256>>>();
    k_thresh1<<<1, 256>>>(w1);
    k_layer1<<<2048, 128>>>();
    k_count_T1<<<400, 256>>>();
    k_thresh2<<<1, 1024>>>(w2);
    k_layer2<<<BATCH / 4, 288>>>();
    k_count_T2<<<144, 256>>>();
    k_thresh3<<<1, 1024>>>(w3, wl, bl);
    k_layer34<<<BATCH / 8, 128>>>(out);
}

// round 7
// speedup vs baseline: 1.3545x; 1.0008x over previous
#include <cuda_runtime.h>
#include <cstdint>
#include <cmath>

#define BATCH 8192

// ---------------- persistent device scratch (no allocations allowed) --------
__device__ uint32_t g_xbits[BATCH * 28];          // [n][p] bits over q (28)
__device__ int      g_T0[28 * 28];                // [q][p]
__device__ unsigned long long g_w1lo[32];
__device__ uint32_t g_w1hi[32];
__device__ int      g_pthr1[32];
__device__ unsigned short g_A1lo[400 * BATCH];    // [pos][n] channels 0..15
__device__ unsigned short g_A1hi[400 * BATCH];    // [pos][n] channels 16..31
__device__ int      g_T1[32 * 400];               // [c][pos]
__device__ uint32_t g_w2b[81 * 16];
__device__ int      g_pthr2[16];
__device__ uint32_t g_A2t[144 * BATCH];           // [pos][n]
__device__ int      g_T2[16 * 144];               // [c][pos]
__device__ uint32_t g_w3b[81 * 8];
__device__ int      g_pthr3[8];
__device__ uint32_t g_wlb[40];
__device__ float    g_bls[10];

// ---------------- input binarize + pack (coalesced float4 reads) -------------
__global__ void k_pack(const float* __restrict__ x) {
    int t = blockIdx.x * blockDim.x + threadIdx.x;   // (n,p) row index
    if (t >= BATCH * 28) return;
    const float4* r = (const float4*)(x + (size_t)t * 28);
    uint32_t w = 0u;
#pragma unroll
    for (int v = 0; v < 7; v++) {
        float4 f = r[v];
        w |= (uint32_t)(f.x >= 0.f) << (v * 4 + 0);
        w |= (uint32_t)(f.y >= 0.f) << (v * 4 + 1);
        w |= (uint32_t)(f.z >= 0.f) << (v * 4 + 2);
        w |= (uint32_t)(f.w >= 0.f) << (v * 4 + 3);
    }
    g_xbits[t] = w;
}

// ---------------- T0 count: block per row p, ballot over samples -------------
__global__ void __launch_bounds__(256) k_count_T0() {
    __shared__ int scnt[28];
    int p = blockIdx.x;
    int t = threadIdx.x, lane = t & 31, warp = t >> 5;
    if (t < 28) scnt[t] = 0;
    __syncthreads();
    int cnt = 0;
    const int per = BATCH / (32 * 8);
    for (int it = 0; it < per; it++) {
        int n = (warp * per + it) * 32 + lane;
        uint32_t v = g_xbits[n * 28 + p];
#pragma unroll
        for (int q = 0; q < 28; q++) {
            uint32_t m = __ballot_sync(0xFFFFFFFFu, (v >> q) & 1u);
            if (lane == q) cnt += __popc(m);
        }
    }
    if (lane < 28) atomicAdd(&scnt[lane], cnt);
    __syncthreads();
    if (t < 28) g_T0[t * 28 + p] = 2 * scnt[t] - BATCH;
}

// ---------------- thresh1: pack w1 + threshold (parallel, smem) --------------
__global__ void __launch_bounds__(256) k_thresh1(const float* __restrict__ w1) {
    __shared__ int sT0[784];
    __shared__ long long U[81];
    int t = threadIdx.x;
    for (int i = t; i < 784; i += 256) sT0[i] = g_T0[i];
    unsigned long long lo = 0ull; uint32_t hi = 0u;
    if (t < 32) {
        for (int i = 0; i < 9; i++)
            for (int j = 0; j < 9; j++) {
                int bit = (w1[t * 81 + i * 9 + j] >= 0.f);
                if (i < 7) lo |= (unsigned long long)bit << (i * 9 + j);
                else       hi |= (uint32_t)bit << ((i - 7) * 9 + j);
            }
        g_w1lo[t] = lo; g_w1hi[t] = hi;
    }
    __syncthreads();
    if (t < 81) {
        int i = t / 9, j = t % 9;
        long long s = 0;
        for (int h = 0; h < 20; h++)
#pragma unroll
            for (int w = 0; w < 20; w++)
                s += sT0[(w + j) * 28 + (h + i)];
        U[t] = s;
    }
    __syncthreads();
    if (t < 32) {
        long long acc = 0;
        for (int ij = 0; ij < 81; ij++) {
            int i = ij / 9, j = ij % 9;
            int bit = (i < 7) ? (int)((lo >> ij) & 1ull)
                              : (int)((hi >> ((i - 7) * 9 + j)) & 1u);
            acc += bit ? U[ij] : -U[ij];
        }
        double m = (double)acc / (8192.0 * 400.0);
        g_pthr1[t] = (int)floor((81.0 - m) * 0.5);
    }
}

// ---------------- layer1: 1->32, split 16-channel x 100-position blocks ------
__global__ void __launch_bounds__(128) k_layer1() {
    __shared__ uint32_t rows[32 * 29];            // padded stride 29: conflict-free
    int t = threadIdx.x, lane = t & 31, warp = t >> 5;
    int bx = blockIdx.x;
    int sg = bx >> 3, pg = bx & 7;
    int cg = pg & 1, pq = pg >> 1;                // 16-chan group, 100-pos group
    int n0 = sg * 32;
    for (int i = t; i < 896; i += 128) {
        int n = i / 28, p = i - n * 28;
        rows[n * 29 + p] = g_xbits[(n0 + n) * 28 + p];
    }
    unsigned long long wlo[16]; uint32_t whi[16]; int thr[16];
#pragma unroll
    for (int k = 0; k < 16; k++) {
        int c = cg * 16 + k;
        wlo[k] = g_w1lo[c]; whi[k] = g_w1hi[c]; thr[k] = g_pthr1[c];
    }
    __syncthreads();
    const uint32_t* r = rows + lane * 29;
    unsigned short* dst = cg ? g_A1hi : g_A1lo;
    for (int pp = 0; pp < 25; pp++) {
        int pos = pq * 100 + warp * 25 + pp;
        int h = pos / 20, w = pos - h * 20;
        uint32_t e[9];
#pragma unroll
        for (int i = 0; i < 9; i++) e[i] = (r[h + i] >> w) & 0x1FFu;
        unsigned long long lo = (unsigned long long)e[0]
            | ((unsigned long long)e[1] << 9)  | ((unsigned long long)e[2] << 18)
            | ((unsigned long long)e[3] << 27) | ((unsigned long long)e[4] << 36)
            | ((unsigned long long)e[5] << 45) | ((unsigned long long)e[6] << 54);
        uint32_t hi = e[7] | (e[8] << 9);
        uint32_t word = 0u;
#pragma unroll
        for (int k = 0; k < 16; k++) {
            int p = __popcll(lo ^ wlo[k]) + __popc(hi ^ whi[k]);
            word |= (uint32_t)(p <= thr[k]) << k;
        }
        dst[(size_t)pos * BATCH + n0 + lane] = (unsigned short)word;
    }
}

// ---------------- T1 count: block per pos, ballot over samples (coalesced) ---
__global__ void __launch_bounds__(256) k_count_T1() {
    __shared__ int scnt[32];
    int pos = blockIdx.x;
    int t = threadIdx.x, lane = t & 31, warp = t >> 5;
    if (t < 32) scnt[t] = 0;
    __syncthreads();
    int cnt = 0;
    const int per = BATCH / 256;
    const size_t base = (size_t)pos * BATCH;
    for (int it = 0; it < per; it++) {
        int n = (warp * per + it) * 32 + lane;
        uint32_t v = (uint32_t)g_A1lo[base + n] | ((uint32_t)g_A1hi[base + n] << 16);
#pragma unroll
        for (int c = 0; c < 32; c++) {
            uint32_t m = __ballot_sync(0xFFFFFFFFu, (v >> c) & 1u);
            if (lane == c) cnt += __popc(m);
        }
    }
    atomicAdd(&scnt[lane], cnt);
    __syncthreads();
    if (t < 32) g_T1[t * 400 + pos] = 2 * scnt[t] - BATCH;
}

// ---------------- thresh2: pack w2b + threshold (parallel, smem) -------------
__global__ void __launch_bounds__(1024) k_thresh2(const float* __restrict__ w2) {
    __shared__ short sT1[12800];
    __shared__ int sU[2592];
    __shared__ uint32_t sw2b[1296];
    int t = threadIdx.x;
    for (int idx = t; idx < 1296; idx += 1024) {
        int ij = idx >> 4, c = idx & 15;
        uint32_t w = 0u;
        for (int k = 0; k < 32; k++)
            w |= (uint32_t)(w2[(c * 32 + k) * 81 + ij] >= 0.f) << k;
        sw2b[idx] = w; g_w2b[idx] = w;
    }
    for (int idx = t; idx < 12800; idx += 1024) sT1[idx] = (short)g_T1[idx];
    __syncthreads();
    for (int idx = t; idx < 2592; idx += 1024) {
        int k = idx / 81, ij = idx % 81, i = ij / 9, j = ij % 9;
        int s = 0;
        const short* base = sT1 + k * 400 + i * 20 + j;
        for (int h = 0; h < 12; h++)
#pragma unroll
            for (int w = 0; w < 12; w++)
                s += base[h * 20 + w];
        sU[idx] = s;
    }
    __syncthreads();
    int warp = t >> 5, lane = t & 31;
    if (warp < 16) {
        int k = lane;
        int a32 = 0;
        for (int ij = 0; ij < 81; ij++) {
            int u = sU[k * 81 + ij];
            a32 += ((sw2b[ij * 16 + warp] >> k) & 1u) ? u : -u;
        }
        long long a = a32;
#pragma unroll
        for (int off = 16; off; off >>= 1)
            a += __shfl_down_sync(0xFFFFFFFFu, a, off);
        if (lane == 0) {
            double m = (double)a / (8192.0 * 144.0);
            g_pthr2[warp] = (int)floor((2592.0 - m) * 0.5);
        }
    }
}

// ---------------- layer 2: 32->16, 20x20 -> 12x12 (hot) ----------------------
// block = 288 threads = 4 samples x 72 workers; worker = (h, 4-wide w tile, 8-chan group)
// j-taps processed in PAIRS so each accumulator update is a single IADD3
// (acc + popc_j + popc_{j+1}): 2.5 ALU inst per popc-trio instead of 3.0.
__global__ void __launch_bounds__(288) k_layer2() {
    __shared__ __align__(16) uint32_t img[4 * 400];
    __shared__ __align__(16) uint32_t wsh[81 * 16];
    __shared__ int spt[16];
    __shared__ uint32_t outw[4 * 144];
    int t = threadIdx.x;
    int n0 = blockIdx.x * 4;
    for (int idx = t; idx < 1600; idx += 288) {
        int pos = idx >> 2, s = idx & 3;
        size_t g = (size_t)pos * BATCH + n0 + s;
        img[s * 400 + pos] = (uint32_t)g_A1lo[g] | ((uint32_t)g_A1hi[g] << 16);
    }
    for (int idx = t; idx < 1296; idx += 288) wsh[idx] = g_w2b[idx];
    if (t < 16) spt[t] = g_pthr2[t];
    for (int idx = t; idx < 576; idx += 288) outw[idx] = 0u;
    __syncthreads();

    int s  = t / 72,  r  = t - s * 72;
    int cg = r / 36,  rr = r - cg * 36;
    int h  = rr / 3,  wt = rr - h * 3;
    int w0 = wt * 4;
    const uint32_t* im = img + s * 400;

    int acc[8][4];
#pragma unroll
    for (int cc = 0; cc < 8; cc++)
#pragma unroll
        for (int ww = 0; ww < 4; ww++) acc[cc][ww] = 0;

    for (int i = 0; i < 9; i++) {
        const uint4* ap = (const uint4*)(im + (h + i) * 20 + w0);
        uint4 a0 = ap[0], a1 = ap[1], a2 = ap[2];
        uint32_t a[12] = {a0.x, a0.y, a0.z, a0.w, a1.x, a1.y, a1.z, a1.w,
                          a2.x, a2.y, a2.z, a2.w};
        const uint4* wrow = (const uint4*)(wsh + i * 9 * 16 + cg * 8);
#pragma unroll
        for (int jp = 0; jp < 4; jp++) {
            int j = jp * 2;
            uint4 wv0 = wrow[j * 4];          // tap j,   this cg (16 words/tap = 4 uint4)
            uint4 wv1 = wrow[j * 4 + 1];
            uint4 xv0 = wrow[(j + 1) * 4];    // tap j+1, this cg
            uint4 xv1 = wrow[(j + 1) * 4 + 1];
            uint32_t wr[8] = {wv0.x, wv0.y, wv0.z, wv0.w, wv1.x, wv1.y, wv1.z, wv1.w};
            uint32_t xr[8] = {xv0.x, xv0.y, xv0.z, xv0.w, xv1.x, xv1.y, xv1.z, xv1.w};
#pragma unroll
            for (int cc = 0; cc < 8; cc++)
#pragma unroll
                for (int ww = 0; ww < 4; ww++)
                    acc[cc][ww] += __popc(a[j + ww] ^ wr[cc])
                                 + __popc(a[j + 1 + ww] ^ xr[cc]);
        }
        {   // j = 8 (odd tap)
            uint4 wv0 = wrow[8 * 4];
            uint4 wv1 = wrow[8 * 4 + 1];
            uint32_t wr[8] = {wv0.x, wv0.y, wv0.z, wv0.w, wv1.x, wv1.y, wv1.z, wv1.w};
#pragma unroll
            for (int cc = 0; cc < 8; cc++)
#pragma unroll
                for (int ww = 0; ww < 4; ww++)
                    acc[cc][ww] += __popc(a[8 + ww] ^ wr[cc]);
        }
    }
#pragma unroll
    for (int ww = 0; ww < 4; ww++) {
        uint32_t byte = 0u;
#pragma unroll
        for (int cc = 0; cc < 8; cc++)
            byte |= (uint32_t)(acc[cc][ww] <= spt[cg * 8 + cc]) << cc;
        atomicOr(&outw[s * 144 + h * 12 + w0 + ww], byte << (cg * 8));
    }
    __syncthreads();
    for (int idx = t; idx < 576; idx += 288) {
        int pos = idx >> 2, ss = idx & 3;
        g_A2t[(size_t)pos * BATCH + n0 + ss] = outw[ss * 144 + pos];
    }
}

// ---------------- T2 count: block per pos, ballot over samples (coalesced) ---
__global__ void __launch_bounds__(256) k_count_T2() {
    __shared__ int scnt[16];
    int pos = blockIdx.x;
    int t = threadIdx.x, lane = t & 31, warp = t >> 5;
    if (t < 16) scnt[t] = 0;
    __syncthreads();
    int cnt = 0;
    const int per = BATCH / (32 * 8);
    for (int it = 0; it < per; it++) {
        int n = (warp * per + it) * 32 + lane;
        uint32_t v = g_A2t[(size_t)pos * BATCH + n];
#pragma unroll
        for (int c = 0; c < 16; c++) {
            uint32_t m = __ballot_sync(0xFFFFFFFFu, (v >> c) & 1u);
            if (lane == c) cnt += __popc(m);
        }
    }
    if (lane < 16) atomicAdd(&scnt[lane], cnt);
    __syncthreads();
    if (t < 16) g_T2[t * 144 + pos] = 2 * scnt[t] - BATCH;
}

// ---------------- thresh3: pack w3b/wl/bl + threshold ------------------------
__global__ void __launch_bounds__(1024) k_thresh3(const float* __restrict__ w3,
                                                  const float* __restrict__ wl,
                                                  const float* __restrict__ bl) {
    __shared__ short sT2[2304];
    __shared__ int sU[16 * 81];
    __shared__ uint32_t sw3b[648];
    int t = threadIdx.x;
    for (int idx = t; idx < 648; idx += 1024) {
        int ij = idx >> 3, c = idx & 7;
        uint32_t w = 0u;
        for (int k = 0; k < 16; k++)
            w |= (uint32_t)(w3[(c * 16 + k) * 81 + ij] >= 0.f) << k;
        sw3b[idx] = w; g_w3b[idx] = w;
    }
    for (int idx = t; idx < 2304; idx += 1024) sT2[idx] = (short)g_T2[idx];
    if (t < 10) {
        for (int tt = 0; tt < 4; tt++) {
            uint32_t w = 0u;
            for (int pos = 0; pos < 16; pos++) {
                w |= (uint32_t)(wl[(t * 8 + 2 * tt)     * 16 + pos] >= 0.f) << pos;
                w |= (uint32_t)(wl[(t * 8 + 2 * tt + 1) * 16 + pos] >= 0.f) << (pos + 16);
            }
            g_wlb[t * 4 + tt] = w;
        }
        g_bls[t] = (bl[t] >= 0.f) ? 1.f : -1.f;
    }
    __syncthreads();
    for (int idx = t; idx < 1296; idx += 1024) {
        int k = idx / 81, ij = idx % 81, i = ij / 9, j = ij % 9;
        int s = 0;
        const short* base = sT2 + k * 144 + i * 12 + j;
#pragma unroll
        for (int h = 0; h < 4; h++)
#pragma unroll
            for (int w = 0; w < 4; w++) s += base[h * 12 + w];
        sU[idx] = s;
    }
    __syncthreads();
    int warp = t >> 5, lane = t & 31;
    if (warp < 8) {
        long long acc = 0;
        if (lane < 16) {
            int k = lane, a = 0;
            for (int ij = 0; ij < 81; ij++) {
                int u = sU[k * 81 + ij];
                a += ((sw3b[ij * 8 + warp] >> k) & 1u) ? u : -u;
            }
            acc = a;
        }
#pragma unroll
        for (int off = 16; off; off >>= 1)
            acc += __shfl_down_sync(0xFFFFFFFFu, acc, off);
        if (lane == 0) {
            double m = (double)acc / (8192.0 * 16.0);
            g_pthr3[warp] = (int)floor((1296.0 - m) * 0.5);
        }
    }
}

// ---------------- layers 3+4 fused -------------------------------------------
__global__ void __launch_bounds__(128) k_layer34(float* __restrict__ out) {
    __shared__ uint32_t img[8 * 144];
    __shared__ __align__(16) uint32_t w3s[81 * 8];
    __shared__ int spt[8];
    __shared__ uint32_t wls[40];
    __shared__ float bls[10];
    int t = threadIdx.x;
    int n0 = blockIdx.x * 8;
    for (int idx = t; idx < 1152; idx += 128) {
        int pos = idx >> 3, s = idx & 7;
        img[s * 144 + pos] = g_A2t[(size_t)pos * BATCH + n0 + s];
    }
    for (int idx = t; idx < 648; idx += 128) w3s[idx] = g_w3b[idx];
    if (t < 8)  spt[t] = g_pthr3[t];
    if (t < 40) wls[t] = g_wlb[t];
    if (t < 10) bls[t] = g_bls[t];
    __syncthreads();

    int warp = t >> 5, lane = t & 31;
    int sb  = warp * 2 + (lane >> 4);
    int pos = lane & 15, h = pos >> 2, w = pos & 3;
    const uint32_t* im = img + sb * 144;

    int acc[8] = {0, 0, 0, 0, 0, 0, 0, 0};
    for (int i = 0; i < 9; i++) {
#pragma unroll
        for (int j = 0; j < 9; j++) {
            uint32_t a = im[(h + i) * 12 + (w + j)];
            const uint4* wp = (const uint4*)(w3s + (i * 9 + j) * 8);
            uint4 w0v = wp[0], w1v = wp[1];
            acc[0] += __popc(a ^ w0v.x); acc[1] += __popc(a ^ w0v.y);
            acc[2] += __popc(a ^ w0v.z); acc[3] += __popc(a ^ w0v.w);
            acc[4] += __popc(a ^ w1v.x); acc[5] += __popc(a ^ w1v.y);
            acc[6] += __popc(a ^ w1v.z); acc[7] += __popc(a ^ w1v.w);
        }
    }
    uint32_t bb[8];
#pragma unroll
    for (int c = 0; c < 8; c++)
        bb[c] = __ballot_sync(0xFFFFFFFFu, acc[c] <= spt[c]);
    int sh = (lane >> 4) * 16;
    uint32_t W[4];
#pragma unroll
    for (int tt = 0; tt < 4; tt++)
        W[tt] = ((bb[2 * tt] >> sh) & 0xFFFFu) | (((bb[2 * tt + 1] >> sh) & 0xFFFFu) << 16);
    if (pos < 10) {
        int cl = pos;
        int sm = __popc(W[0] ^ wls[cl * 4 + 0]) + __popc(W[1] ^ wls[cl * 4 + 1])
               + __popc(W[2] ^ wls[cl * 4 + 2]) + __popc(W[3] ^ wls[cl * 4 + 3]);
        out[(size_t)(n0 + sb) * 10 + cl] = (float)(128 - 2 * sm) + bls[cl];
    }
}

// ---------------- launch ------------------------------------------------------
extern "C" void kernel_launch(void* const* d_in, const int* in_sizes, int n_in,
                              void* d_out, int out_size) {
    const float* x  = (const float*)d_in[0];
    const float* w1 = (const float*)d_in[1];
    const float* w2 = (const float*)d_in[3];
    const float* w3 = (const float*)d_in[5];
    const float* wl = (const float*)d_in[7];
    const float* bl = (const float*)d_in[8];
    float* out = (float*)d_out;

    k_pack<<<(BATCH * 28) / 256, 256>>>(x);
    k_count_T0<<<28, 256>>>();
    k_thresh1<<<1, 256>>>(w1);
    k_layer1<<<2048, 128>>>();
    k_count_T1<<<400, 256>>>();
    k_thresh2<<<1, 1024>>>(w2);
    k_layer2<<<BATCH / 4, 288>>>();
    k_count_T2<<<144, 256>>>();
    k_thresh3<<<1, 1024>>>(w3, wl, bl);
    k_layer34<<<BATCH / 8, 128>>>(out);
}

// round 11
// speedup vs baseline: 1.4617x; 1.0791x over previous
#include <cuda_runtime.h>
#include <cstdint>
#include <cmath>

#define BATCH 8192

// ---------------- persistent device scratch (no allocations allowed) --------
__device__ uint32_t g_xbits[BATCH * 28];          // [n][p] bits over q (28)
__device__ int      g_T0[28 * 28];                // [q][p]
__device__ unsigned long long g_w1lo[32];
__device__ uint32_t g_w1hi[32];
__device__ int      g_pthr1[32];
__device__ unsigned short g_A1lo[400 * BATCH];    // [pos][n] channels 0..15
__device__ unsigned short g_A1hi[400 * BATCH];    // [pos][n] channels 16..31
__device__ int      g_T1[32 * 400];               // [c][pos]
__device__ uint32_t g_w2b[81 * 16];
__device__ int      g_pthr2[16];
__device__ uint32_t g_A2t[144 * BATCH];           // [pos][n]
__device__ int      g_T2[16 * 144];               // [c][pos]
__device__ uint32_t g_w3b[81 * 8];
__device__ int      g_pthr3[8];
__device__ uint32_t g_wlb[40];
__device__ float    g_bls[10];

// ---------------- input binarize + pack (coalesced float4 reads) -------------
__global__ void k_pack(const float* __restrict__ x) {
    int t = blockIdx.x * blockDim.x + threadIdx.x;   // (n,p) row index
    if (t >= BATCH * 28) return;
    const float4* r = (const float4*)(x + (size_t)t * 28);
    uint32_t w = 0u;
#pragma unroll
    for (int v = 0; v < 7; v++) {
        float4 f = r[v];
        w |= (uint32_t)(f.x >= 0.f) << (v * 4 + 0);
        w |= (uint32_t)(f.y >= 0.f) << (v * 4 + 1);
        w |= (uint32_t)(f.z >= 0.f) << (v * 4 + 2);
        w |= (uint32_t)(f.w >= 0.f) << (v * 4 + 3);
    }
    g_xbits[t] = w;
}

// ---------------- T0 count: block per row p, ballot over samples -------------
__global__ void __launch_bounds__(256) k_count_T0() {
    __shared__ int scnt[28];
    int p = blockIdx.x;
    int t = threadIdx.x, lane = t & 31, warp = t >> 5;
    if (t < 28) scnt[t] = 0;
    __syncthreads();
    int cnt = 0;
    const int per = BATCH / (32 * 8);
    for (int it = 0; it < per; it++) {
        int n = (warp * per + it) * 32 + lane;
        uint32_t v = g_xbits[n * 28 + p];
#pragma unroll
        for (int q = 0; q < 28; q++) {
            uint32_t m = __ballot_sync(0xFFFFFFFFu, (v >> q) & 1u);
            if (lane == q) cnt += __popc(m);
        }
    }
    if (lane < 28) atomicAdd(&scnt[lane], cnt);
    __syncthreads();
    if (t < 28) g_T0[t * 28 + p] = 2 * scnt[t] - BATCH;
}

// ---------------- thresh1: pack w1 + threshold (parallel, smem) --------------
__global__ void __launch_bounds__(256) k_thresh1(const float* __restrict__ w1) {
    __shared__ int sT0[784];
    __shared__ long long U[81];
    int t = threadIdx.x;
    for (int i = t; i < 784; i += 256) sT0[i] = g_T0[i];
    unsigned long long lo = 0ull; uint32_t hi = 0u;
    if (t < 32) {
        for (int i = 0; i < 9; i++)
            for (int j = 0; j < 9; j++) {
                int bit = (w1[t * 81 + i * 9 + j] >= 0.f);
                if (i < 7) lo |= (unsigned long long)bit << (i * 9 + j);
                else       hi |= (uint32_t)bit << ((i - 7) * 9 + j);
            }
        g_w1lo[t] = lo; g_w1hi[t] = hi;
    }
    __syncthreads();
    if (t < 81) {
        int i = t / 9, j = t % 9;
        long long s = 0;
        for (int h = 0; h < 20; h++)
#pragma unroll
            for (int w = 0; w < 20; w++)
                s += sT0[(w + j) * 28 + (h + i)];
        U[t] = s;
    }
    __syncthreads();
    if (t < 32) {
        long long acc = 0;
        for (int ij = 0; ij < 81; ij++) {
            int i = ij / 9, j = ij % 9;
            int bit = (i < 7) ? (int)((lo >> ij) & 1ull)
                              : (int)((hi >> ((i - 7) * 9 + j)) & 1u);
            acc += bit ? U[ij] : -U[ij];
        }
        double m = (double)acc / (8192.0 * 400.0);
        g_pthr1[t] = (int)floor((81.0 - m) * 0.5);
    }
}

// ---------------- layer1: 1->32, split 16-channel x 100-position blocks ------
__global__ void __launch_bounds__(128) k_layer1() {
    __shared__ uint32_t rows[32 * 29];            // padded stride 29: conflict-free
    int t = threadIdx.x, lane = t & 31, warp = t >> 5;
    int bx = blockIdx.x;
    int sg = bx >> 3, pg = bx & 7;
    int cg = pg & 1, pq = pg >> 1;                // 16-chan group, 100-pos group
    int n0 = sg * 32;
    for (int i = t; i < 896; i += 128) {
        int n = i / 28, p = i - n * 28;
        rows[n * 29 + p] = g_xbits[(n0 + n) * 28 + p];
    }
    unsigned long long wlo[16]; uint32_t whi[16]; int thr[16];
#pragma unroll
    for (int k = 0; k < 16; k++) {
        int c = cg * 16 + k;
        wlo[k] = g_w1lo[c]; whi[k] = g_w1hi[c]; thr[k] = g_pthr1[c];
    }
    __syncthreads();
    const uint32_t* r = rows + lane * 29;
    unsigned short* dst = cg ? g_A1hi : g_A1lo;
    for (int pp = 0; pp < 25; pp++) {
        int pos = pq * 100 + warp * 25 + pp;
        int h = pos / 20, w = pos - h * 20;
        uint32_t e[9];
#pragma unroll
        for (int i = 0; i < 9; i++) e[i] = (r[h + i] >> w) & 0x1FFu;
        unsigned long long lo = (unsigned long long)e[0]
            | ((unsigned long long)e[1] << 9)  | ((unsigned long long)e[2] << 18)
            | ((unsigned long long)e[3] << 27) | ((unsigned long long)e[4] << 36)
            | ((unsigned long long)e[5] << 45) | ((unsigned long long)e[6] << 54);
        uint32_t hi = e[7] | (e[8] << 9);
        uint32_t word = 0u;
#pragma unroll
        for (int k = 0; k < 16; k++) {
            int p = __popcll(lo ^ wlo[k]) + __popc(hi ^ whi[k]);
            word |= (uint32_t)(p <= thr[k]) << k;
        }
        dst[(size_t)pos * BATCH + n0 + lane] = (unsigned short)word;
    }
}

// ---------------- T1 count: block per pos, ballot over samples (coalesced) ---
__global__ void __launch_bounds__(256) k_count_T1() {
    __shared__ int scnt[32];
    int pos = blockIdx.x;
    int t = threadIdx.x, lane = t & 31, warp = t >> 5;
    if (t < 32) scnt[t] = 0;
    __syncthreads();
    int cnt = 0;
    const int per = BATCH / 256;
    const size_t base = (size_t)pos * BATCH;
    for (int it = 0; it < per; it++) {
        int n = (warp * per + it) * 32 + lane;
        uint32_t v = (uint32_t)g_A1lo[base + n] | ((uint32_t)g_A1hi[base + n] << 16);
#pragma unroll
        for (int c = 0; c < 32; c++) {
            uint32_t m = __ballot_sync(0xFFFFFFFFu, (v >> c) & 1u);
            if (lane == c) cnt += __popc(m);
        }
    }
    atomicAdd(&scnt[lane], cnt);
    __syncthreads();
    if (t < 32) g_T1[t * 400 + pos] = 2 * scnt[t] - BATCH;
}

// ---------------- thresh2: pack w2b + threshold (parallel, smem) -------------
__global__ void __launch_bounds__(1024) k_thresh2(const float* __restrict__ w2) {
    __shared__ short sT1[12800];
    __shared__ int sU[2592];
    __shared__ uint32_t sw2b[1296];
    int t = threadIdx.x;
    for (int idx = t; idx < 1296; idx += 1024) {
        int ij = idx >> 4, c = idx & 15;
        uint32_t w = 0u;
        for (int k = 0; k < 32; k++)
            w |= (uint32_t)(w2[(c * 32 + k) * 81 + ij] >= 0.f) << k;
        sw2b[idx] = w; g_w2b[idx] = w;
    }
    for (int idx = t; idx < 12800; idx += 1024) sT1[idx] = (short)g_T1[idx];
    __syncthreads();
    for (int idx = t; idx < 2592; idx += 1024) {
        int k = idx / 81, ij = idx % 81, i = ij / 9, j = ij % 9;
        int s = 0;
        const short* base = sT1 + k * 400 + i * 20 + j;
        for (int h = 0; h < 12; h++)
#pragma unroll
            for (int w = 0; w < 12; w++)
                s += base[h * 20 + w];
        sU[idx] = s;
    }
    __syncthreads();
    int warp = t >> 5, lane = t & 31;
    if (warp < 16) {
        int k = lane;
        int a32 = 0;
        for (int ij = 0; ij < 81; ij++) {
            int u = sU[k * 81 + ij];
            a32 += ((sw2b[ij * 16 + warp] >> k) & 1u) ? u : -u;
        }
        long long a = a32;
#pragma unroll
        for (int off = 16; off; off >>= 1)
            a += __shfl_down_sync(0xFFFFFFFFu, a, off);
        if (lane == 0) {
            double m = (double)a / (8192.0 * 144.0);
            g_pthr2[warp] = (int)floor((2592.0 - m) * 0.5);
        }
    }
}

// ---------------- layer 2: 32->16, 20x20 -> 12x12 (hot) ----------------------
// block = 288 threads = 4 samples x 72 workers; worker = (h, 4-wide w tile, 8-chan group)
// CSA 3:2 compression over j-tap TRIPLES: s=x^y^z, c=maj(x,y,z) -> only 2 POPCs
// per 3 taps (33% fewer POPCs). S and C accumulated separately, packed 2/reg;
// total = S + 2*C at the epilogue.
__global__ void __launch_bounds__(288) k_layer2() {
    __shared__ __align__(16) uint32_t img[4 * 400];
    __shared__ __align__(16) uint32_t wsh[81 * 16];
    __shared__ int spt[16];
    __shared__ uint32_t outw[4 * 144];
    int t = threadIdx.x;
    int n0 = blockIdx.x * 4;
    for (int idx = t; idx < 1600; idx += 288) {
        int pos = idx >> 2, s = idx & 3;
        size_t g = (size_t)pos * BATCH + n0 + s;
        img[s * 400 + pos] = (uint32_t)g_A1lo[g] | ((uint32_t)g_A1hi[g] << 16);
    }
    for (int idx = t; idx < 1296; idx += 288) wsh[idx] = g_w2b[idx];
    if (t < 16) spt[t] = g_pthr2[t];
    for (int idx = t; idx < 576; idx += 288) outw[idx] = 0u;
    __syncthreads();

    int s  = t / 72,  r  = t - s * 72;
    int cg = r / 36,  rr = r - cg * 36;
    int h  = rr / 3,  wt = rr - h * 3;
    int w0 = wt * 4;
    const uint32_t* im = img + s * 400;

    // packed accumulators: [chan][wpair] halves = (ww even | ww odd << 16)
    uint32_t accS[8][2], accC[8][2];
#pragma unroll
    for (int cc = 0; cc < 8; cc++) {
        accS[cc][0] = accS[cc][1] = 0u;
        accC[cc][0] = accC[cc][1] = 0u;
    }

    for (int i = 0; i < 9; i++) {
        const uint4* ap = (const uint4*)(im + (h + i) * 20 + w0);
        uint4 a0 = ap[0], a1 = ap[1], a2 = ap[2];
        uint32_t a[12] = {a0.x, a0.y, a0.z, a0.w, a1.x, a1.y, a1.z, a1.w,
                          a2.x, a2.y, a2.z, a2.w};
        const uint4* wrow = (const uint4*)wsh + i * 36 + cg * 2;
#pragma unroll
        for (int tr = 0; tr < 3; tr++) {
            int j = tr * 3;
            uint4 u0 = wrow[(j + 0) * 4], u1 = wrow[(j + 0) * 4 + 1];
            uint4 v0 = wrow[(j + 1) * 4], v1 = wrow[(j + 1) * 4 + 1];
            uint4 q0 = wrow[(j + 2) * 4], q1 = wrow[(j + 2) * 4 + 1];
            uint32_t wx[8] = {u0.x, u0.y, u0.z, u0.w, u1.x, u1.y, u1.z, u1.w};
            uint32_t wy[8] = {v0.x, v0.y, v0.z, v0.w, v1.x, v1.y, v1.z, v1.w};
            uint32_t wz[8] = {q0.x, q0.y, q0.z, q0.w, q1.x, q1.y, q1.z, q1.w};
#pragma unroll
            for (int cc = 0; cc < 8; cc++) {
                uint32_t ps[4], pc[4];
#pragma unroll
                for (int ww = 0; ww < 4; ww++) {
                    uint32_t x = a[j + 0 + ww] ^ wx[cc];
                    uint32_t y = a[j + 1 + ww] ^ wy[cc];
                    uint32_t z = a[j + 2 + ww] ^ wz[cc];
                    uint32_t sm = x ^ y ^ z;                    // 1 LOP3
                    uint32_t cy = (x & y) | (z & (x | y));      // 1 LOP3 (maj)
                    ps[ww] = __popc(sm);
                    pc[ww] = __popc(cy);
                }
                accS[cc][0] += ps[0] + (ps[1] << 16);
                accS[cc][1] += ps[2] + (ps[3] << 16);
                accC[cc][0] += pc[0] + (pc[1] << 16);
                accC[cc][1] += pc[2] + (pc[3] << 16);
            }
        }
    }
#pragma unroll
    for (int ww = 0; ww < 4; ww++) {
        uint32_t byte = 0u;
#pragma unroll
        for (int cc = 0; cc < 8; cc++) {
            int sv = (ww & 1) ? (int)(accS[cc][ww >> 1] >> 16)
                              : (int)(accS[cc][ww >> 1] & 0xFFFFu);
            int cv = (ww & 1) ? (int)(accC[cc][ww >> 1] >> 16)
                              : (int)(accC[cc][ww >> 1] & 0xFFFFu);
            int v = sv + 2 * cv;
            byte |= (uint32_t)(v <= spt[cg * 8 + cc]) << cc;
        }
        atomicOr(&outw[s * 144 + h * 12 + w0 + ww], byte << (cg * 8));
    }
    __syncthreads();
    for (int idx = t; idx < 576; idx += 288) {
        int pos = idx >> 2, ss = idx & 3;
        g_A2t[(size_t)pos * BATCH + n0 + ss] = outw[ss * 144 + pos];
    }
}

// ---------------- T2 count: block per pos, ballot over samples (coalesced) ---
__global__ void __launch_bounds__(256) k_count_T2() {
    __shared__ int scnt[16];
    int pos = blockIdx.x;
    int t = threadIdx.x, lane = t & 31, warp = t >> 5;
    if (t < 16) scnt[t] = 0;
    __syncthreads();
    int cnt = 0;
    const int per = BATCH / (32 * 8);
    for (int it = 0; it < per; it++) {
        int n = (warp * per + it) * 32 + lane;
        uint32_t v = g_A2t[(size_t)pos * BATCH + n];
#pragma unroll
        for (int c = 0; c < 16; c++) {
            uint32_t m = __ballot_sync(0xFFFFFFFFu, (v >> c) & 1u);
            if (lane == c) cnt += __popc(m);
        }
    }
    if (lane < 16) atomicAdd(&scnt[lane], cnt);
    __syncthreads();
    if (t < 16) g_T2[t * 144 + pos] = 2 * scnt[t] - BATCH;
}

// ---------------- thresh3: pack w3b/wl/bl + threshold ------------------------
__global__ void __launch_bounds__(1024) k_thresh3(const float* __restrict__ w3,
                                                  const float* __restrict__ wl,
                                                  const float* __restrict__ bl) {
    __shared__ short sT2[2304];
    __shared__ int sU[16 * 81];
    __shared__ uint32_t sw3b[648];
    int t = threadIdx.x;
    for (int idx = t; idx < 648; idx += 1024) {
        int ij = idx >> 3, c = idx & 7;
        uint32_t w = 0u;
        for (int k = 0; k < 16; k++)
            w |= (uint32_t)(w3[(c * 16 + k) * 81 + ij] >= 0.f) << k;
        sw3b[idx] = w; g_w3b[idx] = w;
    }
    for (int idx = t; idx < 2304; idx += 1024) sT2[idx] = (short)g_T2[idx];
    if (t < 10) {
        for (int tt = 0; tt < 4; tt++) {
            uint32_t w = 0u;
            for (int pos = 0; pos < 16; pos++) {
                w |= (uint32_t)(wl[(t * 8 + 2 * tt)     * 16 + pos] >= 0.f) << pos;
                w |= (uint32_t)(wl[(t * 8 + 2 * tt + 1) * 16 + pos] >= 0.f) << (pos + 16);
            }
            g_wlb[t * 4 + tt] = w;
        }
        g_bls[t] = (bl[t] >= 0.f) ? 1.f : -1.f;
    }
    __syncthreads();
    for (int idx = t; idx < 1296; idx += 1024) {
        int k = idx / 81, ij = idx % 81, i = ij / 9, j = ij % 9;
        int s = 0;
        const short* base = sT2 + k * 144 + i * 12 + j;
#pragma unroll
        for (int h = 0; h < 4; h++)
#pragma unroll
            for (int w = 0; w < 4; w++) s += base[h * 12 + w];
        sU[idx] = s;
    }
    __syncthreads();
    int warp = t >> 5, lane = t & 31;
    if (warp < 8) {
        long long acc = 0;
        if (lane < 16) {
            int k = lane, a = 0;
            for (int ij = 0; ij < 81; ij++) {
                int u = sU[k * 81 + ij];
                a += ((sw3b[ij * 8 + warp] >> k) & 1u) ? u : -u;
            }
            acc = a;
        }
#pragma unroll
        for (int off = 16; off; off >>= 1)
            acc += __shfl_down_sync(0xFFFFFFFFu, acc, off);
        if (lane == 0) {
            double m = (double)acc / (8192.0 * 16.0);
            g_pthr3[warp] = (int)floor((1296.0 - m) * 0.5);
        }
    }
}

// ---------------- layers 3+4 fused -------------------------------------------
__global__ void __launch_bounds__(128) k_layer34(float* __restrict__ out) {
    __shared__ uint32_t img[8 * 144];
    __shared__ __align__(16) uint32_t w3s[81 * 8];
    __shared__ int spt[8];
    __shared__ uint32_t wls[40];
    __shared__ float bls[10];
    int t = threadIdx.x;
    int n0 = blockIdx.x * 8;
    for (int idx = t; idx < 1152; idx += 128) {
        int pos = idx >> 3, s = idx & 7;
        img[s * 144 + pos] = g_A2t[(size_t)pos * BATCH + n0 + s];
    }
    for (int idx = t; idx < 648; idx += 128) w3s[idx] = g_w3b[idx];
    if (t < 8)  spt[t] = g_pthr3[t];
    if (t < 40) wls[t] = g_wlb[t];
    if (t < 10) bls[t] = g_bls[t];
    __syncthreads();

    int warp = t >> 5, lane = t & 31;
    int sb  = warp * 2 + (lane >> 4);
    int pos = lane & 15, h = pos >> 2, w = pos & 3;
    const uint32_t* im = img + sb * 144;

    int acc[8] = {0, 0, 0, 0, 0, 0, 0, 0};
    for (int i = 0; i < 9; i++) {
#pragma unroll
        for (int j = 0; j < 9; j++) {
            uint32_t a = im[(h + i) * 12 + (w + j)];
            const uint4* wp = (const uint4*)(w3s + (i * 9 + j) * 8);
            uint4 w0v = wp[0], w1v = wp[1];
            acc[0] += __popc(a ^ w0v.x); acc[1] += __popc(a ^ w0v.y);
            acc[2] += __popc(a ^ w0v.z); acc[3] += __popc(a ^ w0v.w);
            acc[4] += __popc(a ^ w1v.x); acc[5] += __popc(a ^ w1v.y);
            acc[6] += __popc(a ^ w1v.z); acc[7] += __popc(a ^ w1v.w);
        }
    }
    uint32_t bb[8];
#pragma unroll
    for (int c = 0; c < 8; c++)
        bb[c] = __ballot_sync(0xFFFFFFFFu, acc[c] <= spt[c]);
    int sh = (lane >> 4) * 16;
    uint32_t W[4];
#pragma unroll
    for (int tt = 0; tt < 4; tt++)
        W[tt] = ((bb[2 * tt] >> sh) & 0xFFFFu) | (((bb[2 * tt + 1] >> sh) & 0xFFFFu) << 16);
    if (pos < 10) {
        int cl = pos;
        int sm = __popc(W[0] ^ wls[cl * 4 + 0]) + __popc(W[1] ^ wls[cl * 4 + 1])
               + __popc(W[2] ^ wls[cl * 4 + 2]) + __popc(W[3] ^ wls[cl * 4 + 3]);
        out[(size_t)(n0 + sb) * 10 + cl] = (float)(128 - 2 * sm) + bls[cl];
    }
}

// ---------------- launch ------------------------------------------------------
extern "C" void kernel_launch(void* const* d_in, const int* in_sizes, int n_in,
                              void* d_out, int out_size) {
    const float* x  = (const float*)d_in[0];
    const float* w1 = (const float*)d_in[1];
    const float* w2 = (const float*)d_in[3];
    const float* w3 = (const float*)d_in[5];
    const float* wl = (const float*)d_in[7];
    const float* bl = (const float*)d_in[8];
    float* out = (float*)d_out;

    k_pack<<<(BATCH * 28) / 256, 256>>>(x);
    k_count_T0<<<28, 256>>>();
    k_thresh1<<<1, 256>>>(w1);
    k_layer1<<<2048, 128>>>();
    k_count_T1<<<400, 256>>>();
    k_thresh2<<<1, 1024>>>(w2);
    k_layer2<<<BATCH / 4, 288>>>();
    k_count_T2<<<144, 256>>>();
    k_thresh3<<<1, 1024>>>(w3, wl, bl);
    k_layer34<<<BATCH / 8, 128>>>(out);
}